// round 11
// baseline (speedup 1.0000x reference)
#include <cuda_runtime.h>
#include <cuda_bf16.h>
#include <math.h>
#include <stdint.h>

#define BB   16
#define ENCL 64
#define HH   96
#define EE   128
#define VV   32000

#define JCH  4          // j per chunk
#define NJC  24         // chunks (4*24 = 96)

typedef unsigned long long ull;

// ---------------- scratch (device globals; no allocation allowed) ------------
__device__ float g_part[NJC][BB * ENCL * HH];      // 9.4 MB partials
__device__ float g_wt[96 * 64 * 68];               // compacted tf32 weights
__device__ float g_emb[BB * EE];
__device__ float g_dec1[BB * HH];
__device__ float g_cvg1[BB * ENCL];
__device__ float g_cvgcol[ENCL * ENCL];
__device__ float g_o[BB * HH];
__device__ float g_psumT[BB * 256];
__device__ float g_lse[BB];
__device__ float g_warmsink[4 * 256];
__device__ int   g_ctr;
__device__ int   g_flag;
__device__ int   g_done;

// ---------------- helpers ---------------------------------------------------
__device__ __forceinline__ float sigmoid_fast(float x) {
    return __fdividef(1.0f, 1.0f + __expf(-x));
}
__device__ __forceinline__ float tanh_precise(float x) {
    float e = __expf(2.0f * x);
    return 1.0f - __fdividef(2.0f, e + 1.0f);
}
__device__ __forceinline__ float tanh_apx(float x) {
    float y; asm("tanh.approx.f32 %0, %1;" : "=f"(y) : "f"(x)); return y;
}
__device__ __forceinline__ uint32_t f2tf32(float x) {
    uint32_t r; asm("cvt.rna.tf32.f32 %0, %1;" : "=r"(r) : "f"(x)); return r;
}
__device__ __forceinline__ uint32_t smem_u32(const void* p) {
    return (uint32_t)__cvta_generic_to_shared(p);
}
#define CP_A4(dst,src)  asm volatile("cp.async.ca.shared.global [%0], [%1], 4;"::"r"(dst),"l"(src))
#define CP_A16(dst,src) asm volatile("cp.async.cg.shared.global [%0], [%1], 16;"::"r"(dst),"l"(src))
#define CP_COMMIT()     asm volatile("cp.async.commit_group;")
#define CP_WAIT0()      asm volatile("cp.async.wait_group 0;")

__device__ __forceinline__ void mma_tf32(float* c,
                                         uint32_t a0, uint32_t a1, uint32_t a2, uint32_t a3,
                                         uint32_t b0, uint32_t b1) {
    asm("mma.sync.aligned.m16n8k8.row.col.f32.tf32.tf32.f32 "
        "{%0,%1,%2,%3}, {%4,%5,%6,%7}, {%8,%9}, {%0,%1,%2,%3};"
        : "+f"(c[0]), "+f"(c[1]), "+f"(c[2]), "+f"(c[3])
        : "r"(a0), "r"(a1), "r"(a2), "r"(a3), "r"(b0), "r"(b1));
}
template <int N4>
__device__ __forceinline__ float dotT(const float* __restrict__ row,
                                      const float* __restrict__ vec) {
    float a0 = 0.f, a1 = 0.f, a2 = 0.f, a3 = 0.f;
    const float4* r4 = (const float4*)row;
    #pragma unroll
    for (int q = 0; q < N4; q++) {
        float4 w = __ldg(&r4[q]);
        const float* vv = vec + q * 4;
        a0 += w.x * vv[0]; a1 += w.y * vv[1];
        a2 += w.z * vv[2]; a3 += w.w * vv[3];
    }
    return (a0 + a1) + (a2 + a3);
}

// ============================================================================
// K0: weight-slice compaction (spread over 64 blocks) + pre-work + L2 warm.
// Grid 70 x 256: bid<64 gather (each thread = quarter (o,i) row, 6 float4);
// 64 emb/dec1; 65 cvg; 66-69 warm.
// ============================================================================
__global__ void __launch_bounds__(256)
k0_gather(const float* __restrict__ attn_w,
          const int*   __restrict__ input_ids,
          const float* __restrict__ emb,
          const float* __restrict__ hidden,
          const float* __restrict__ W_dec,
          const float* __restrict__ b_dec,
          const float* __restrict__ coverage,
          const float* __restrict__ cvg_w,
          const float* __restrict__ cvg_b,
          const float* __restrict__ w_ih,
          const float* __restrict__ w_hh,
          const float* __restrict__ W_new,
          const float* __restrict__ W_pre)
{
    __shared__ float sm[5200];
    const int bid = blockIdx.x;
    const int tid = threadIdx.x;

    if (bid < 64) {
        const int t = bid * 256 + tid;            // 0..16383
        const int pair = t >> 2;                  // o*64+i
        const int qs = (t & 3) * 6;               // float4 offset within row
        const int o = pair >> 6, i = pair & 63;
        const int dst_oi = o * 68 + i;
        const float4* src = (const float4*)(attn_w + (size_t)pair * 9216 + 4512) + qs;
        #pragma unroll
        for (int q = 0; q < 6; q++) {
            float4 tv = __ldg(&src[q]);
            const int j = (qs + q) * 4;
            g_wt[(j + 0) * 4352 + dst_oi] = __uint_as_float(f2tf32(tv.x));
            g_wt[(j + 1) * 4352 + dst_oi] = __uint_as_float(f2tf32(tv.y));
            g_wt[(j + 2) * 4352 + dst_oi] = __uint_as_float(f2tf32(tv.z));
            g_wt[(j + 3) * 4352 + dst_oi] = __uint_as_float(f2tf32(tv.w));
        }
        return;
    }
    if (bid == 64) {
        for (int idx = tid; idx < BB * EE; idx += 256) {
            int b = idx >> 7, k = idx & 127;
            g_emb[idx] = emb[(long)input_ids[b] * EE + k];
        }
        float* s_hid = sm;
        for (int idx = tid; idx < BB * HH; idx += 256) s_hid[idx] = hidden[idx];
        __syncthreads();
        const int warp = tid >> 5, lane = tid & 31;
        for (int rr = warp; rr < BB * HH; rr += 8) {
            int b = rr / HH, h = rr % HH;
            const float* wr = W_dec + h * HH;
            const float* hr = s_hid + b * HH;
            float p = 0.f;
            #pragma unroll
            for (int kk = 0; kk < HH; kk += 32) p += wr[kk + lane] * hr[kk + lane];
            #pragma unroll
            for (int o = 16; o; o >>= 1) p += __shfl_xor_sync(0xffffffffu, p, o);
            if (lane == 0) g_dec1[rr] = p + b_dec[h];
        }
    } else if (bid == 65) {
        float* s_col = sm;            // 64*64
        float* s_cov = sm + 4096;     // 16*64
        for (int idx = tid; idx < ENCL * ENCL; idx += 256) {
            float val = cvg_w[idx * HH + 47];
            s_col[idx] = val;
            g_cvgcol[idx] = val;
        }
        for (int idx = tid; idx < BB * ENCL; idx += 256) s_cov[idx] = coverage[idx];
        __syncthreads();
        for (int idx = tid; idx < BB * ENCL; idx += 256) {
            int b = idx >> 6, o = idx & 63;
            float acc = cvg_b[o];
            const float* cr = s_cov + b * ENCL;
            const float* wc = s_col + o * ENCL;
            #pragma unroll 8
            for (int i = 0; i < ENCL; i++) acc += cr[i] * wc[i];
            g_cvg1[idx] = acc;
        }
    } else {
        const int wb = bid - 66;
        const float4* src = nullptr; int n4 = 0;
        if (wb == 0) { src = (const float4*)w_ih;  n4 = 288 * 24; }
        else if (wb == 1) { src = (const float4*)w_hh;  n4 = 288 * 24; }
        else if (wb == 2) { src = (const float4*)W_new; n4 = 96 * 56; }
        else { src = (const float4*)W_pre; n4 = 96 * 48; }
        float s = 0.f;
        for (int i = tid; i < n4; i += 256) {
            float4 t = __ldg(&src[i]);
            s += t.x + t.y + t.z + t.w;
        }
        if (wb == 3) {
            const float4* wd = (const float4*)W_dec;
            for (int i = tid; i < 96 * 24; i += 256) {
                float4 t = __ldg(&wd[i]);
                s += t.x + t.y + t.z + t.w;
            }
        }
        g_warmsink[wb * 256 + tid] = s;
    }
}

// ============================================================================
// K1: enc_feat conv partials via tf32 mma.sync.
// Grid 384 = (b:16 x jc:24, 4 j each).  256 threads, 2 blocks/SM.
// smem: xs[64][104] + ws[4][64][68] = 96,256B.  Staging via cp.async
// (x kept as raw fp32 bits — tf32 mma ignores the low mantissa bits).
// ============================================================================
__global__ void __launch_bounds__(256, 2)
k1_mma(const float* __restrict__ enc_out)
{
    extern __shared__ float sm[];
    const int bid = blockIdx.x;
    const int tid = threadIdx.x;

    const int b  = bid / NJC;
    const int jc = bid % NJC;
    const int j0 = jc * JCH;

    float* xs = sm;              // [64][104]
    float* ws = sm + 64 * 104;   // [4][64][68]

    // stage x window: cp.async interior, STS-zero borders (disjoint addrs)
    {
        const uint32_t xs_s = smem_u32(xs);
        for (int idx = tid; idx < 64 * 104; idx += 256) {
            int i = idx / 104, c = idx - 104 * i;
            int xc = j0 + c - 47;
            if ((unsigned)xc < 96u) {
                CP_A4(xs_s + idx * 4, enc_out + (b * ENCL + i) * HH + xc);
            } else {
                xs[idx] = 0.0f;
            }
        }
    }
    // stage weights: contiguous 16B cp.async from g_wt
    {
        const uint32_t ws_s = smem_u32(ws);
        const float4* wsrc = (const float4*)g_wt + (size_t)j0 * 1088 + tid;
        #pragma unroll
        for (int q = 0; q < 17; q++)
            CP_A16(ws_s + (tid + q * 256) * 16, wsrc + q * 256);
    }
    CP_COMMIT();
    CP_WAIT0();
    __syncthreads();

    const int warp = tid >> 5, lane = tid & 31;
    const int o0  = (warp >> 2) * 32;
    const int w0  = (warp & 3) * 24;
    const int qr  = lane >> 2, qc = lane & 3;

    float c[2][3][4];
    #pragma unroll
    for (int s = 0; s < 2; s++)
        #pragma unroll
        for (int t = 0; t < 3; t++)
            #pragma unroll
            for (int u = 0; u < 4; u++) c[s][t][u] = 0.0f;

    #pragma unroll
    for (int jj = 0; jj < JCH; jj++) {
        const float* wsj = ws + jj * 4352;
        const int colbase = w0 + qr + jj;
        #pragma unroll
        for (int k0 = 0; k0 < 64; k0 += 8) {
            uint32_t a[2][4];
            #pragma unroll
            for (int s = 0; s < 2; s++) {
                const float* wrow = wsj + (o0 + s * 16 + qr) * 68 + k0 + qc;
                a[s][0] = __float_as_uint(wrow[0]);
                a[s][1] = __float_as_uint(wrow[8 * 68]);
                a[s][2] = __float_as_uint(wrow[4]);
                a[s][3] = __float_as_uint(wrow[8 * 68 + 4]);
            }
            const float* xrow0 = xs + (k0 + qc) * 104 + colbase;
            const float* xrow1 = xrow0 + 4 * 104;
            #pragma unroll
            for (int t = 0; t < 3; t++) {
                uint32_t b0 = __float_as_uint(xrow0[t * 8]);
                uint32_t b1 = __float_as_uint(xrow1[t * 8]);
                mma_tf32(c[0][t], a[0][0], a[0][1], a[0][2], a[0][3], b0, b1);
                mma_tf32(c[1][t], a[1][0], a[1][1], a[1][2], a[1][3], b0, b1);
            }
        }
    }

    float* dst = g_part[jc] + b * (ENCL * HH);
    #pragma unroll
    for (int s = 0; s < 2; s++) {
        #pragma unroll
        for (int t = 0; t < 3; t++) {
            int wcol = w0 + t * 8 + 2 * qc;
            int orow = o0 + s * 16 + qr;
            *(float2*)(dst + orow * HH + wcol)       = make_float2(c[s][t][0], c[s][t][1]);
            *(float2*)(dst + (orow + 8) * HH + wcol) = make_float2(c[s][t][2], c[s][t][3]);
        }
    }
}

// ============================================================================
// K2: per-batch MEGA kernel. 16 blocks x 256.
// ============================================================================
__global__ void __launch_bounds__(256, 1)
k2_mega(const float* __restrict__ enc_out,
        const float* __restrict__ coverage,
        const float* __restrict__ hidden,
        const float* __restrict__ W_new,
        const float* __restrict__ b_new,
        const float* __restrict__ w_ih,
        const float* __restrict__ w_hh,
        const float* __restrict__ b_ih,
        const float* __restrict__ b_hh,
        const float* __restrict__ W_dec,
        const float* __restrict__ b_dec,
        const float* __restrict__ cvg_b,
        const float* __restrict__ v,
        const float* __restrict__ attn_b,
        const float* __restrict__ b_pre,
        const float* __restrict__ W_pre,
        float* __restrict__ out_hidden,
        float* __restrict__ out_ctx2,
        float* __restrict__ out_aw2,
        float* __restrict__ out_cov2)
{
    extern __shared__ float dyn[];
    float* s_eo = dyn;                 // [64][96]
    float* s_ef = dyn + ENCL * HH;     // [64][96]
    __shared__ float s_h[HH], s_v[HH], s_dec[HH], s_x[HH], s_hnew[HH];
    __shared__ float s_ab[ENCL], s_cvg1[ENCL], s_cvg2[ENCL];
    __shared__ float s_aw[ENCL], s_cov1[ENCL], s_sc[ENCL];
    __shared__ __align__(16) float s_cat[EE + HH];
    __shared__ float s_gi[3 * HH], s_gh[3 * HH];

    const int b = blockIdx.x;
    const int tid = threadIdx.x;
    const int warp = tid >> 5, lane = tid & 31;

    // ---- phase 1: independent loads ----
    if (tid < 64)       s_ab[tid] = attn_b[tid];
    else if (tid < 160) s_h[tid - 64] = hidden[b * HH + tid - 64];
    else                s_v[tid - 160] = v[b * HH + tid - 160];
    if (tid < 96)       s_dec[tid] = g_dec1[b * HH + tid];
    else if (tid < 224) s_cat[tid - 96] = g_emb[b * EE + (tid - 96)];
    if (tid < 64)       s_cvg1[tid] = g_cvg1[b * ENCL + tid];

    {
        const float4* eo4 = (const float4*)(enc_out + b * ENCL * HH);
        float4* s_eo4 = (float4*)s_eo;
        float4* s_ef4 = (float4*)s_ef;
        #pragma unroll
        for (int q = 0; q < 6; q++)
            s_eo4[tid + q * 256] = __ldg(&eo4[tid + q * 256]);
        #pragma unroll
        for (int q = 0; q < 6; q++) {
            const int i4 = tid + q * 256;
            float4 acc = __ldg((const float4*)(g_part[0] + b * ENCL * HH) + i4);
            #pragma unroll
            for (int cdx = 1; cdx < NJC; cdx++) {
                float4 p = __ldg((const float4*)(g_part[cdx] + b * ENCL * HH) + i4);
                acc.x += p.x; acc.y += p.y; acc.z += p.z; acc.w += p.w;
            }
            s_ef4[i4] = acc;
        }
    }
    __syncthreads();

    // ---- phase 2: scores1 ----
    #pragma unroll
    for (int q = 0; q < 8; q++) {
        const int e = warp * 8 + q;
        const float cf = s_cvg1[e] + s_ab[e];
        float acc = 0.f;
        #pragma unroll
        for (int kk = 0; kk < HH; kk += 32) {
            int h = kk + lane;
            acc += tanh_apx(s_ef[e * HH + h] + s_dec[h] + cf) * s_v[h];
        }
        #pragma unroll
        for (int o = 16; o; o >>= 1) acc += __shfl_xor_sync(0xffffffffu, acc, o);
        if (lane == 0) s_sc[e] = acc;
    }
    __syncthreads();

    // ---- phase 3: warp7 softmax1; warps 0-6 compute gh ----
    if (warp == 7) {
        float a0 = s_sc[lane], a1 = s_sc[lane + 32];
        float m = fmaxf(a0, a1);
        #pragma unroll
        for (int o = 16; o; o >>= 1) m = fmaxf(m, __shfl_xor_sync(0xffffffffu, m, o));
        float e0 = __expf(a0 - m), e1 = __expf(a1 - m);
        float s = e0 + e1;
        #pragma unroll
        for (int o = 16; o; o >>= 1) s += __shfl_xor_sync(0xffffffffu, s, o);
        float inv = __fdividef(1.0f, s);
        s_aw[lane] = e0 * inv; s_aw[lane + 32] = e1 * inv;
    } else {
        int rr = warp * 32 + lane;
        s_gh[rr] = dotT<24>(w_hh + rr * HH, s_h) + b_hh[rr];
        if (rr < 64) {
            int r2 = 224 + rr;
            s_gh[r2] = dotT<24>(w_hh + r2 * HH, s_h) + b_hh[r2];
        }
    }
    __syncthreads();

    // ---- phase 4: cov1 + ctx1 ----
    if (tid < ENCL) s_cov1[tid] = coverage[b * ENCL + tid] + s_aw[tid];
    if (tid < HH) {
        float acc = 0.f;
        #pragma unroll 8
        for (int e = 0; e < ENCL; e++) acc += s_aw[e] * s_eo[e * HH + tid];
        s_cat[EE + tid] = acc;
    }
    __syncthreads();

    // ---- phase 5: x ----
    if (tid < HH) s_x[tid] = dotT<56>(W_new + tid * (EE + HH), s_cat) + b_new[tid];
    __syncthreads();

    // ---- phase 6: gi ----
    s_gi[tid] = dotT<24>(w_ih + tid * HH, s_x) + b_ih[tid];
    if (tid < 32) {
        int r2 = 256 + tid;
        s_gi[r2] = dotT<24>(w_ih + r2 * HH, s_x) + b_ih[r2];
    }
    __syncthreads();

    // ---- phase 7: gates ----
    if (tid < HH) {
        float r = sigmoid_fast(s_gi[tid] + s_gh[tid]);
        float z = sigmoid_fast(s_gi[HH + tid] + s_gh[HH + tid]);
        float n = tanh_precise(s_gi[2 * HH + tid] + r * s_gh[2 * HH + tid]);
        float hn = (1.0f - z) * n + z * s_h[tid];
        s_hnew[tid] = hn;
        s_cat[tid] = hn;
        out_hidden[b * HH + tid] = hn;
    }
    __syncthreads();

    // ---- phase 8: dec2 + cvg2 ----
    if (tid < HH) {
        s_dec[tid] = dotT<24>(W_dec + tid * HH, s_hnew) + b_dec[tid];
    } else if (tid < HH + ENCL) {
        const int o = tid - HH;
        s_cvg2[o] = dotT<16>(g_cvgcol + o * ENCL, s_cov1) + cvg_b[o];
    }
    __syncthreads();

    // ---- phase 9: scores2 ----
    #pragma unroll
    for (int q = 0; q < 8; q++) {
        const int e = warp * 8 + q;
        const float cf = s_cvg2[e] + s_ab[e];
        float acc = 0.f;
        #pragma unroll
        for (int kk = 0; kk < HH; kk += 32) {
            int h = kk + lane;
            acc += tanh_apx(s_ef[e * HH + h] + s_dec[h] + cf) * s_v[h];
        }
        #pragma unroll
        for (int o = 16; o; o >>= 1) acc += __shfl_xor_sync(0xffffffffu, acc, o);
        if (lane == 0) s_sc[e] = acc;
    }
    __syncthreads();

    // ---- phase 10: softmax2 ----
    if (warp == 7) {
        float a0 = s_sc[lane], a1 = s_sc[lane + 32];
        float m = fmaxf(a0, a1);
        #pragma unroll
        for (int o = 16; o; o >>= 1) m = fmaxf(m, __shfl_xor_sync(0xffffffffu, m, o));
        float e0 = __expf(a0 - m), e1 = __expf(a1 - m);
        float s = e0 + e1;
        #pragma unroll
        for (int o = 16; o; o >>= 1) s += __shfl_xor_sync(0xffffffffu, s, o);
        float inv = __fdividef(1.0f, s);
        s_aw[lane] = e0 * inv; s_aw[lane + 32] = e1 * inv;
    }
    __syncthreads();

    // ---- phase 11: outputs + ctx2 ----
    if (tid < ENCL) {
        float aw = s_aw[tid];
        out_aw2[b * ENCL + tid] = aw;
        out_cov2[b * ENCL + tid] = s_cov1[tid] + aw;
    }
    if (tid < HH) {
        float acc = 0.f;
        #pragma unroll 8
        for (int e = 0; e < ENCL; e++) acc += s_aw[e] * s_eo[e * HH + tid];
        s_cat[HH + tid] = acc;
        out_ctx2[b * HH + tid] = acc;
    }
    __syncthreads();

    // ---- phase 12: o ----
    if (tid < HH)
        g_o[b * HH + tid] = tanh_precise(
            dotT<48>(W_pre + tid * (2 * HH), s_cat) + b_pre[tid]);
}

// ============================================================================
// K3: logits + fused log_softmax finalize (spin barrier; 250 blocks resident).
// Deep prefetch: 8 rows (24 LDG) in flight per lane.
// ============================================================================
__global__ void __launch_bounds__(256, 2)
k3_logits(const float* __restrict__ W_out, const float* __restrict__ b_out,
          float* __restrict__ out_logp)
{
    __shared__ float s_so[HH][BB];
    __shared__ float s_log[BB][132];
    __shared__ float s_lse[BB];
    __shared__ int   s_ticket;
    const int tid = threadIdx.x, warp = tid >> 5, lane = tid & 31;

    for (int idx = tid; idx < BB * HH; idx += 256) {
        int bb = idx / HH, h = idx % HH;
        s_so[h][bb] = g_o[idx];
    }
    __syncthreads();

    float sA[16], sB[16], sC[16];
    #pragma unroll
    for (int q = 0; q < 4; q++) {
        float4 t0 = ((const float4*)s_so[lane])[q];
        float4 t1 = ((const float4*)s_so[lane + 32])[q];
        float4 t2 = ((const float4*)s_so[lane + 64])[q];
        sA[q*4+0]=t0.x; sA[q*4+1]=t0.y; sA[q*4+2]=t0.z; sA[q*4+3]=t0.w;
        sB[q*4+0]=t1.x; sB[q*4+1]=t1.y; sB[q*4+2]=t1.z; sB[q*4+3]=t1.w;
        sC[q*4+0]=t2.x; sC[q*4+1]=t2.y; sC[q*4+2]=t2.z; sC[q*4+3]=t2.w;
    }

    const int rowBase = blockIdx.x * 128 + warp * 16;

    // preload 8 rows (24 outstanding LDG per lane)
    float p0[8], p1[8], p2[8];
    #pragma unroll
    for (int r = 0; r < 8; r++) {
        const float* wr = W_out + (size_t)(rowBase + r) * HH;
        p0[r] = __ldg(wr + lane);
        p1[r] = __ldg(wr + lane + 32);
        p2[r] = __ldg(wr + lane + 64);
    }

    #pragma unroll
    for (int half = 0; half < 2; half++) {
        #pragma unroll
        for (int r = 0; r < 8; r++) {
            float cw0 = p0[r], cw1 = p1[r], cw2 = p2[r];
            if (half == 0) {   // stream next 8 rows while computing
                const float* wr = W_out + (size_t)(rowBase + 8 + r) * HH;
                p0[r] = __ldg(wr + lane);
                p1[r] = __ldg(wr + lane + 32);
                p2[r] = __ldg(wr + lane + 64);
            }
            const int rl = half * 8 + r;

            float a[16];
            #pragma unroll
            for (int bb = 0; bb < 16; bb++) a[bb] = cw0 * sA[bb] + cw1 * sB[bb] + cw2 * sC[bb];

            #pragma unroll
            for (int i = 0; i < 8; i++) {
                float send = (lane & 16) ? a[i] : a[i + 8];
                float rec  = __shfl_xor_sync(0xffffffffu, send, 16);
                float keep = (lane & 16) ? a[i + 8] : a[i];
                a[i] = keep + rec;
            }
            #pragma unroll
            for (int i = 0; i < 4; i++) {
                float send = (lane & 8) ? a[i] : a[i + 4];
                float rec  = __shfl_xor_sync(0xffffffffu, send, 8);
                float keep = (lane & 8) ? a[i + 4] : a[i];
                a[i] = keep + rec;
            }
            #pragma unroll
            for (int i = 0; i < 2; i++) {
                float send = (lane & 4) ? a[i] : a[i + 2];
                float rec  = __shfl_xor_sync(0xffffffffu, send, 4);
                float keep = (lane & 4) ? a[i + 2] : a[i];
                a[i] = keep + rec;
            }
            {
                float send = (lane & 2) ? a[0] : a[1];
                float rec  = __shfl_xor_sync(0xffffffffu, send, 2);
                float keep = (lane & 2) ? a[1] : a[0];
                a[0] = keep + rec;
            }
            float val = a[0] + __shfl_xor_sync(0xffffffffu, a[0], 1);
            val += b_out[rowBase + rl];
            if ((lane & 1) == 0) s_log[(lane >> 1) & 15][warp * 16 + rl] = val;
        }
    }
    __syncthreads();

    {
        int bb = tid >> 4, j0 = tid & 15;
        float s = 0.f;
        #pragma unroll
        for (int j = j0; j < 128; j += 16) s += __expf(s_log[bb][j]);
        #pragma unroll
        for (int o = 8; o; o >>= 1) s += __shfl_xor_sync(0xffffffffu, s, o);
        if (j0 == 0) g_psumT[bb * 256 + blockIdx.x] = s;
    }
    __threadfence();
    if (tid == 0) s_ticket = atomicAdd(&g_ctr, 1);
    __syncthreads();

    if (s_ticket == 249) {
        for (int bb = warp; bb < BB; bb += 8) {
            float s = 0.f;
            for (int p = lane; p < 250; p += 32) s += g_psumT[bb * 256 + p];
            #pragma unroll
            for (int o = 16; o; o >>= 1) s += __shfl_xor_sync(0xffffffffu, s, o);
            if (lane == 0) g_lse[bb] = __logf(s);
        }
        __syncthreads();
        __threadfence();
        if (tid == 0) atomicExch(&g_flag, 1);
    }

    if (tid == 0) {
        volatile int* vf = &g_flag;
        while (*vf == 0) __nanosleep(64);
    }
    __syncthreads();
    __threadfence();
    if (tid < BB) s_lse[tid] = g_lse[tid];
    __syncthreads();

    const int base = blockIdx.x * 128;
    for (int idx = tid; idx < 2048; idx += 256) {
        int bb = idx >> 7, j = idx & 127;
        out_logp[bb * VV + base + j] = s_log[bb][j] - s_lse[bb];
    }

    __threadfence();
    if (tid == 0) {
        int d = atomicAdd(&g_done, 1);
        if (d == 249) { g_ctr = 0; g_flag = 0; g_done = 0; }
    }
}

// ============================================================================
extern "C" void kernel_launch(void* const* d_in, const int* in_sizes, int n_in,
                              void* d_out, int out_size)
{
    const float* encoder_outputs = (const float*)d_in[0];
    const int*   input_ids       = (const int*)  d_in[1];
    const float* hidden          = (const float*)d_in[2];
    const float* coverage        = (const float*)d_in[3];
    const float* emb             = (const float*)d_in[4];
    const float* W_dec           = (const float*)d_in[5];
    const float* b_dec           = (const float*)d_in[6];
    const float* attn_w          = (const float*)d_in[7];
    const float* attn_b          = (const float*)d_in[8];
    const float* cvg_w           = (const float*)d_in[9];
    const float* cvg_b           = (const float*)d_in[10];
    const float* v               = (const float*)d_in[11];
    const float* W_new           = (const float*)d_in[12];
    const float* b_new           = (const float*)d_in[13];
    const float* w_ih            = (const float*)d_in[14];
    const float* w_hh            = (const float*)d_in[15];
    const float* b_ih            = (const float*)d_in[16];
    const float* b_hh            = (const float*)d_in[17];
    const float* W_pre           = (const float*)d_in[18];
    const float* b_pre           = (const float*)d_in[19];
    const float* W_out           = (const float*)d_in[20];
    const float* b_out           = (const float*)d_in[21];

    float* out = (float*)d_out;
    float* out_logp   = out;
    float* out_hidden = out + BB * VV;
    float* out_ctx2   = out_hidden + BB * HH;
    float* out_aw2    = out_ctx2 + BB * HH;
    float* out_cov2   = out_aw2 + BB * ENCL;

    const int mma_smem = (64 * 104 + JCH * 64 * 68) * (int)sizeof(float);  // 96,256
    cudaFuncSetAttribute(k1_mma, cudaFuncAttributeMaxDynamicSharedMemorySize, mma_smem);
    const int k2_smem = 2 * ENCL * HH * (int)sizeof(float);                // 49,152
    cudaFuncSetAttribute(k2_mega, cudaFuncAttributeMaxDynamicSharedMemorySize, k2_smem);

    k0_gather<<<70, 256>>>(attn_w, input_ids, emb, hidden, W_dec, b_dec,
                           coverage, cvg_w, cvg_b, w_ih, w_hh, W_new, W_pre);

    k1_mma<<<16 * NJC, 256, mma_smem>>>(encoder_outputs);

    k2_mega<<<BB, 256, k2_smem>>>(encoder_outputs, coverage, hidden,
                                  W_new, b_new, w_ih, w_hh, b_ih, b_hh,
                                  W_dec, b_dec, cvg_b, v, attn_b, b_pre, W_pre,
                                  out_hidden, out_ctx2, out_aw2, out_cov2);

    k3_logits<<<250, 256>>>(W_out, b_out, out_logp);
}

// round 12
// speedup vs baseline: 1.5608x; 1.5608x over previous
#include <cuda_runtime.h>
#include <cuda_bf16.h>
#include <math.h>
#include <stdint.h>

#define BB   16
#define ENCL 64
#define HH   96
#define EE   128
#define VV   32000

#define JCH  8          // j per chunk
#define NJC  12         // chunks (8*12 = 96)

typedef unsigned long long ull;

// ---------------- scratch (device globals; no allocation allowed) ------------
__device__ float g_part[NJC][BB * ENCL * HH];
__device__ float g_emb[BB * EE];
__device__ float g_dec1[BB * HH];
__device__ float g_cvg1[BB * ENCL];
__device__ float g_cvgcol[ENCL * ENCL];
__device__ float g_o[BB * HH];
__device__ float g_psumT[BB * 256];
__device__ float g_lse[BB];
__device__ float g_warmsink[4 * 256];
__device__ int   g_ctr;
__device__ int   g_flag;
__device__ int   g_done;

// ---------------- helpers ---------------------------------------------------
__device__ __forceinline__ float sigmoid_fast(float x) {
    return __fdividef(1.0f, 1.0f + __expf(-x));
}
__device__ __forceinline__ float tanh_precise(float x) {
    float e = __expf(2.0f * x);
    return 1.0f - __fdividef(2.0f, e + 1.0f);
}
__device__ __forceinline__ float tanh_apx(float x) {
    float y; asm("tanh.approx.f32 %0, %1;" : "=f"(y) : "f"(x)); return y;
}
__device__ __forceinline__ uint32_t f2tf32(float x) {
    uint32_t r; asm("cvt.rna.tf32.f32 %0, %1;" : "=r"(r) : "f"(x)); return r;
}
__device__ __forceinline__ void mma_tf32(float* c,
                                         uint32_t a0, uint32_t a1, uint32_t a2, uint32_t a3,
                                         uint32_t b0, uint32_t b1) {
    asm("mma.sync.aligned.m16n8k8.row.col.f32.tf32.tf32.f32 "
        "{%0,%1,%2,%3}, {%4,%5,%6,%7}, {%8,%9}, {%0,%1,%2,%3};"
        : "+f"(c[0]), "+f"(c[1]), "+f"(c[2]), "+f"(c[3])
        : "r"(a0), "r"(a1), "r"(a2), "r"(a3), "r"(b0), "r"(b1));
}
template <int N4>
__device__ __forceinline__ float dotT(const float* __restrict__ row,
                                      const float* __restrict__ vec) {
    float a0 = 0.f, a1 = 0.f, a2 = 0.f, a3 = 0.f;
    const float4* r4 = (const float4*)row;
    #pragma unroll
    for (int q = 0; q < N4; q++) {
        float4 w = __ldg(&r4[q]);
        const float* vv = vec + q * 4;
        a0 += w.x * vv[0]; a1 += w.y * vv[1];
        a2 += w.z * vv[2]; a3 += w.w * vv[3];
    }
    return (a0 + a1) + (a2 + a3);
}

// ============================================================================
// K1: enc_feat conv partials via tf32 mma.sync + pre-work + L2 warming.
// Grid: 192 mma blocks + 2 pre + 4 warm.  256 threads.  (R9-identical)
// ============================================================================
__global__ void __launch_bounds__(256)
k1_mma(const float* __restrict__ enc_out,
       const float* __restrict__ attn_w,
       const int*   __restrict__ input_ids,
       const float* __restrict__ emb,
       const float* __restrict__ hidden,
       const float* __restrict__ W_dec,
       const float* __restrict__ b_dec,
       const float* __restrict__ coverage,
       const float* __restrict__ cvg_w,
       const float* __restrict__ cvg_b,
       const float* __restrict__ w_ih,
       const float* __restrict__ w_hh,
       const float* __restrict__ W_new,
       const float* __restrict__ W_pre)
{
    extern __shared__ float sm[];
    const int bid = blockIdx.x;
    const int tid = threadIdx.x;

    if (bid >= 16 * NJC) {
        if (bid == 16 * NJC) {
            for (int idx = tid; idx < BB * EE; idx += 256) {
                int b = idx >> 7, k = idx & 127;
                g_emb[idx] = emb[(long)input_ids[b] * EE + k];
            }
            float* s_hid = sm;
            for (int idx = tid; idx < BB * HH; idx += 256) s_hid[idx] = hidden[idx];
            __syncthreads();
            const int warp = tid >> 5, lane = tid & 31;
            for (int rr = warp; rr < BB * HH; rr += 8) {
                int b = rr / HH, h = rr % HH;
                const float* wr = W_dec + h * HH;
                const float* hr = s_hid + b * HH;
                float p = 0.f;
                #pragma unroll
                for (int kk = 0; kk < HH; kk += 32) p += wr[kk + lane] * hr[kk + lane];
                #pragma unroll
                for (int o = 16; o; o >>= 1) p += __shfl_xor_sync(0xffffffffu, p, o);
                if (lane == 0) g_dec1[rr] = p + b_dec[h];
            }
        } else if (bid == 16 * NJC + 1) {
            float* s_col = sm;
            float* s_cov = sm + 4096;
            for (int idx = tid; idx < ENCL * ENCL; idx += 256) {
                float val = cvg_w[idx * HH + 47];
                s_col[idx] = val;
                g_cvgcol[idx] = val;
            }
            for (int idx = tid; idx < BB * ENCL; idx += 256) s_cov[idx] = coverage[idx];
            __syncthreads();
            for (int idx = tid; idx < BB * ENCL; idx += 256) {
                int b = idx >> 6, o = idx & 63;
                float acc = cvg_b[o];
                const float* cr = s_cov + b * ENCL;
                const float* wc = s_col + o * ENCL;
                #pragma unroll 8
                for (int i = 0; i < ENCL; i++) acc += cr[i] * wc[i];
                g_cvg1[idx] = acc;
            }
        } else {
            const int wb = bid - (16 * NJC + 2);
            const float4* src = nullptr; int n4 = 0;
            if (wb == 0) { src = (const float4*)w_ih;  n4 = 288 * 24; }
            else if (wb == 1) { src = (const float4*)w_hh;  n4 = 288 * 24; }
            else if (wb == 2) { src = (const float4*)W_new; n4 = 96 * 56; }
            else { src = (const float4*)W_pre; n4 = 96 * 48; }
            float s = 0.f;
            for (int i = tid; i < n4; i += 256) {
                float4 t = __ldg(&src[i]);
                s += t.x + t.y + t.z + t.w;
            }
            if (wb == 3) {
                const float4* wd = (const float4*)W_dec;
                for (int i = tid; i < 96 * 24; i += 256) {
                    float4 t = __ldg(&wd[i]);
                    s += t.x + t.y + t.z + t.w;
                }
            }
            g_warmsink[wb * 256 + tid] = s;
        }
        return;
    }

    const int b  = bid / NJC;
    const int jc = bid % NJC;
    const int j0 = jc * JCH;

    float* xs = sm;              // [64][104]
    float* ws = sm + 64 * 104;   // [8][64][68]

    for (int idx = tid; idx < 64 * 104; idx += 256) {
        int i = idx / 104, c = idx % 104;
        int xc = j0 + c - 47;
        float vv = (xc >= 0 && xc < 96) ? enc_out[(b * ENCL + i) * HH + xc] : 0.0f;
        xs[idx] = __uint_as_float(f2tf32(vv));
    }
    for (int idx = tid; idx < 4096; idx += 256) {
        int o = idx >> 6, i = idx & 63;
        const float* p = attn_w + ((size_t)(o * ENCL + i) * HH + 47) * HH + j0;
        float4 v0 = *(const float4*)(p);
        float4 v1 = *(const float4*)(p + 4);
        float* dst = ws + o * 68 + i;
        dst[0 * 4352] = __uint_as_float(f2tf32(v0.x));
        dst[1 * 4352] = __uint_as_float(f2tf32(v0.y));
        dst[2 * 4352] = __uint_as_float(f2tf32(v0.z));
        dst[3 * 4352] = __uint_as_float(f2tf32(v0.w));
        dst[4 * 4352] = __uint_as_float(f2tf32(v1.x));
        dst[5 * 4352] = __uint_as_float(f2tf32(v1.y));
        dst[6 * 4352] = __uint_as_float(f2tf32(v1.z));
        dst[7 * 4352] = __uint_as_float(f2tf32(v1.w));
    }
    __syncthreads();

    const int warp = tid >> 5, lane = tid & 31;
    const int o0  = (warp >> 2) * 32;
    const int w0  = (warp & 3) * 24;
    const int qr  = lane >> 2, qc = lane & 3;

    float c[2][3][4];
    #pragma unroll
    for (int s = 0; s < 2; s++)
        #pragma unroll
        for (int t = 0; t < 3; t++)
            #pragma unroll
            for (int u = 0; u < 4; u++) c[s][t][u] = 0.0f;

    #pragma unroll 1
    for (int jj = 0; jj < JCH; jj++) {
        const float* wsj = ws + jj * 4352;
        const int colbase = w0 + qr + jj;
        #pragma unroll
        for (int k0 = 0; k0 < 64; k0 += 8) {
            uint32_t a[2][4];
            #pragma unroll
            for (int s = 0; s < 2; s++) {
                const float* wrow = wsj + (o0 + s * 16 + qr) * 68 + k0 + qc;
                a[s][0] = __float_as_uint(wrow[0]);
                a[s][1] = __float_as_uint(wrow[8 * 68]);
                a[s][2] = __float_as_uint(wrow[4]);
                a[s][3] = __float_as_uint(wrow[8 * 68 + 4]);
            }
            const float* xrow0 = xs + (k0 + qc) * 104 + colbase;
            const float* xrow1 = xrow0 + 4 * 104;
            #pragma unroll
            for (int t = 0; t < 3; t++) {
                uint32_t b0 = __float_as_uint(xrow0[t * 8]);
                uint32_t b1 = __float_as_uint(xrow1[t * 8]);
                mma_tf32(c[0][t], a[0][0], a[0][1], a[0][2], a[0][3], b0, b1);
                mma_tf32(c[1][t], a[1][0], a[1][1], a[1][2], a[1][3], b0, b1);
            }
        }
    }

    float* dst = g_part[jc] + b * (ENCL * HH);
    #pragma unroll
    for (int s = 0; s < 2; s++) {
        #pragma unroll
        for (int t = 0; t < 3; t++) {
            int wcol = w0 + t * 8 + 2 * qc;
            int orow = o0 + s * 16 + qr;
            *(float2*)(dst + orow * HH + wcol)       = make_float2(c[s][t][0], c[s][t][1]);
            *(float2*)(dst + (orow + 8) * HH + wcol) = make_float2(c[s][t][2], c[s][t][3]);
        }
    }
}

// ============================================================================
// K2: per-batch MEGA kernel. 16 blocks x 256.  (R9-identical)
// ============================================================================
__global__ void __launch_bounds__(256, 1)
k2_mega(const float* __restrict__ enc_out,
        const float* __restrict__ coverage,
        const float* __restrict__ hidden,
        const float* __restrict__ W_new,
        const float* __restrict__ b_new,
        const float* __restrict__ w_ih,
        const float* __restrict__ w_hh,
        const float* __restrict__ b_ih,
        const float* __restrict__ b_hh,
        const float* __restrict__ W_dec,
        const float* __restrict__ b_dec,
        const float* __restrict__ cvg_b,
        const float* __restrict__ v,
        const float* __restrict__ attn_b,
        const float* __restrict__ b_pre,
        const float* __restrict__ W_pre,
        float* __restrict__ out_hidden,
        float* __restrict__ out_ctx2,
        float* __restrict__ out_aw2,
        float* __restrict__ out_cov2)
{
    extern __shared__ float dyn[];
    float* s_eo = dyn;                 // [64][96]
    float* s_ef = dyn + ENCL * HH;     // [64][96]
    __shared__ float s_h[HH], s_v[HH], s_dec[HH], s_x[HH], s_hnew[HH];
    __shared__ float s_ab[ENCL], s_cvg1[ENCL], s_cvg2[ENCL];
    __shared__ float s_aw[ENCL], s_cov1[ENCL], s_sc[ENCL];
    __shared__ __align__(16) float s_cat[EE + HH];
    __shared__ float s_gi[3 * HH], s_gh[3 * HH];

    const int b = blockIdx.x;
    const int tid = threadIdx.x;
    const int warp = tid >> 5, lane = tid & 31;

    // ---- phase 1: independent loads ----
    if (tid < 64)       s_ab[tid] = attn_b[tid];
    else if (tid < 160) s_h[tid - 64] = hidden[b * HH + tid - 64];
    else                s_v[tid - 160] = v[b * HH + tid - 160];
    if (tid < 96)       s_dec[tid] = g_dec1[b * HH + tid];
    else if (tid < 224) s_cat[tid - 96] = g_emb[b * EE + (tid - 96)];
    if (tid < 64)       s_cvg1[tid] = g_cvg1[b * ENCL + tid];

    {
        const float4* eo4 = (const float4*)(enc_out + b * ENCL * HH);
        float4* s_eo4 = (float4*)s_eo;
        float4* s_ef4 = (float4*)s_ef;
        #pragma unroll
        for (int q = 0; q < 6; q++)
            s_eo4[tid + q * 256] = __ldg(&eo4[tid + q * 256]);
        #pragma unroll
        for (int q = 0; q < 6; q++) {
            const int i4 = tid + q * 256;
            float4 acc = __ldg((const float4*)(g_part[0] + b * ENCL * HH) + i4);
            #pragma unroll
            for (int cdx = 1; cdx < NJC; cdx++) {
                float4 p = __ldg((const float4*)(g_part[cdx] + b * ENCL * HH) + i4);
                acc.x += p.x; acc.y += p.y; acc.z += p.z; acc.w += p.w;
            }
            s_ef4[i4] = acc;
        }
    }
    __syncthreads();

    // ---- phase 2: scores1 ----
    #pragma unroll
    for (int q = 0; q < 8; q++) {
        const int e = warp * 8 + q;
        const float cf = s_cvg1[e] + s_ab[e];
        float acc = 0.f;
        #pragma unroll
        for (int kk = 0; kk < HH; kk += 32) {
            int h = kk + lane;
            acc += tanh_apx(s_ef[e * HH + h] + s_dec[h] + cf) * s_v[h];
        }
        #pragma unroll
        for (int o = 16; o; o >>= 1) acc += __shfl_xor_sync(0xffffffffu, acc, o);
        if (lane == 0) s_sc[e] = acc;
    }
    __syncthreads();

    // ---- phase 3: warp7 softmax1; warps 0-6 compute gh ----
    if (warp == 7) {
        float a0 = s_sc[lane], a1 = s_sc[lane + 32];
        float m = fmaxf(a0, a1);
        #pragma unroll
        for (int o = 16; o; o >>= 1) m = fmaxf(m, __shfl_xor_sync(0xffffffffu, m, o));
        float e0 = __expf(a0 - m), e1 = __expf(a1 - m);
        float s = e0 + e1;
        #pragma unroll
        for (int o = 16; o; o >>= 1) s += __shfl_xor_sync(0xffffffffu, s, o);
        float inv = __fdividef(1.0f, s);
        s_aw[lane] = e0 * inv; s_aw[lane + 32] = e1 * inv;
    } else {
        int rr = warp * 32 + lane;
        s_gh[rr] = dotT<24>(w_hh + rr * HH, s_h) + b_hh[rr];
        if (rr < 64) {
            int r2 = 224 + rr;
            s_gh[r2] = dotT<24>(w_hh + r2 * HH, s_h) + b_hh[r2];
        }
    }
    __syncthreads();

    // ---- phase 4: cov1 + ctx1 ----
    if (tid < ENCL) s_cov1[tid] = coverage[b * ENCL + tid] + s_aw[tid];
    if (tid < HH) {
        float acc = 0.f;
        #pragma unroll 8
        for (int e = 0; e < ENCL; e++) acc += s_aw[e] * s_eo[e * HH + tid];
        s_cat[EE + tid] = acc;
    }
    __syncthreads();

    // ---- phase 5: x ----
    if (tid < HH) s_x[tid] = dotT<56>(W_new + tid * (EE + HH), s_cat) + b_new[tid];
    __syncthreads();

    // ---- phase 6: gi ----
    s_gi[tid] = dotT<24>(w_ih + tid * HH, s_x) + b_ih[tid];
    if (tid < 32) {
        int r2 = 256 + tid;
        s_gi[r2] = dotT<24>(w_ih + r2 * HH, s_x) + b_ih[r2];
    }
    __syncthreads();

    // ---- phase 7: gates ----
    if (tid < HH) {
        float r = sigmoid_fast(s_gi[tid] + s_gh[tid]);
        float z = sigmoid_fast(s_gi[HH + tid] + s_gh[HH + tid]);
        float n = tanh_precise(s_gi[2 * HH + tid] + r * s_gh[2 * HH + tid]);
        float hn = (1.0f - z) * n + z * s_h[tid];
        s_hnew[tid] = hn;
        s_cat[tid] = hn;
        out_hidden[b * HH + tid] = hn;
    }
    __syncthreads();

    // ---- phase 8: dec2 + cvg2 ----
    if (tid < HH) {
        s_dec[tid] = dotT<24>(W_dec + tid * HH, s_hnew) + b_dec[tid];
    } else if (tid < HH + ENCL) {
        const int o = tid - HH;
        s_cvg2[o] = dotT<16>(g_cvgcol + o * ENCL, s_cov1) + cvg_b[o];
    }
    __syncthreads();

    // ---- phase 9: scores2 ----
    #pragma unroll
    for (int q = 0; q < 8; q++) {
        const int e = warp * 8 + q;
        const float cf = s_cvg2[e] + s_ab[e];
        float acc = 0.f;
        #pragma unroll
        for (int kk = 0; kk < HH; kk += 32) {
            int h = kk + lane;
            acc += tanh_apx(s_ef[e * HH + h] + s_dec[h] + cf) * s_v[h];
        }
        #pragma unroll
        for (int o = 16; o; o >>= 1) acc += __shfl_xor_sync(0xffffffffu, acc, o);
        if (lane == 0) s_sc[e] = acc;
    }
    __syncthreads();

    // ---- phase 10: softmax2 ----
    if (warp == 7) {
        float a0 = s_sc[lane], a1 = s_sc[lane + 32];
        float m = fmaxf(a0, a1);
        #pragma unroll
        for (int o = 16; o; o >>= 1) m = fmaxf(m, __shfl_xor_sync(0xffffffffu, m, o));
        float e0 = __expf(a0 - m), e1 = __expf(a1 - m);
        float s = e0 + e1;
        #pragma unroll
        for (int o = 16; o; o >>= 1) s += __shfl_xor_sync(0xffffffffu, s, o);
        float inv = __fdividef(1.0f, s);
        s_aw[lane] = e0 * inv; s_aw[lane + 32] = e1 * inv;
    }
    __syncthreads();

    // ---- phase 11: outputs + ctx2 ----
    if (tid < ENCL) {
        float aw = s_aw[tid];
        out_aw2[b * ENCL + tid] = aw;
        out_cov2[b * ENCL + tid] = s_cov1[tid] + aw;
    }
    if (tid < HH) {
        float acc = 0.f;
        #pragma unroll 8
        for (int e = 0; e < ENCL; e++) acc += s_aw[e] * s_eo[e * HH + tid];
        s_cat[HH + tid] = acc;
        out_ctx2[b * HH + tid] = acc;
    }
    __syncthreads();

    // ---- phase 12: o ----
    if (tid < HH)
        g_o[b * HH + tid] = tanh_precise(
            dotT<48>(W_pre + tid * (2 * HH), s_cat) + b_pre[tid]);
}

// ============================================================================
// K3: logits + fused log_softmax finalize (spin barrier; 250 blocks resident).
// 4-row rolling prefetch (12 regs, ~12 LDG in flight) + float4 final write.
// ============================================================================
__global__ void __launch_bounds__(256, 2)
k3_logits(const float* __restrict__ W_out, const float* __restrict__ b_out,
          float* __restrict__ out_logp)
{
    __shared__ float s_so[HH][BB];
    __shared__ __align__(16) float s_log[BB][132];
    __shared__ float s_lse[BB];
    __shared__ int   s_ticket;
    const int tid = threadIdx.x, warp = tid >> 5, lane = tid & 31;

    for (int idx = tid; idx < BB * HH; idx += 256) {
        int bb = idx / HH, h = idx % HH;
        s_so[h][bb] = g_o[idx];
    }
    __syncthreads();

    float sA[16], sB[16], sC[16];
    #pragma unroll
    for (int q = 0; q < 4; q++) {
        float4 t0 = ((const float4*)s_so[lane])[q];
        float4 t1 = ((const float4*)s_so[lane + 32])[q];
        float4 t2 = ((const float4*)s_so[lane + 64])[q];
        sA[q*4+0]=t0.x; sA[q*4+1]=t0.y; sA[q*4+2]=t0.z; sA[q*4+3]=t0.w;
        sB[q*4+0]=t1.x; sB[q*4+1]=t1.y; sB[q*4+2]=t1.z; sB[q*4+3]=t1.w;
        sC[q*4+0]=t2.x; sC[q*4+1]=t2.y; sC[q*4+2]=t2.z; sC[q*4+3]=t2.w;
    }

    const int rowBase = blockIdx.x * 128 + warp * 16;

    // 4-row rolling prefetch window (12 regs)
    float p0[4], p1[4], p2[4];
    #pragma unroll
    for (int r = 0; r < 4; r++) {
        const float* wr = W_out + (size_t)(rowBase + r) * HH;
        p0[r] = __ldg(wr + lane);
        p1[r] = __ldg(wr + lane + 32);
        p2[r] = __ldg(wr + lane + 64);
    }

    #pragma unroll
    for (int g = 0; g < 4; g++) {
        #pragma unroll
        for (int r = 0; r < 4; r++) {
            float cw0 = p0[r], cw1 = p1[r], cw2 = p2[r];
            if (g < 3) {   // refill this slot with the row 4 ahead
                const float* wr = W_out + (size_t)(rowBase + (g + 1) * 4 + r) * HH;
                p0[r] = __ldg(wr + lane);
                p1[r] = __ldg(wr + lane + 32);
                p2[r] = __ldg(wr + lane + 64);
            }
            const int rl = g * 4 + r;

            float a[16];
            #pragma unroll
            for (int bb = 0; bb < 16; bb++) a[bb] = cw0 * sA[bb] + cw1 * sB[bb] + cw2 * sC[bb];

            #pragma unroll
            for (int i = 0; i < 8; i++) {
                float send = (lane & 16) ? a[i] : a[i + 8];
                float rec  = __shfl_xor_sync(0xffffffffu, send, 16);
                float keep = (lane & 16) ? a[i + 8] : a[i];
                a[i] = keep + rec;
            }
            #pragma unroll
            for (int i = 0; i < 4; i++) {
                float send = (lane & 8) ? a[i] : a[i + 4];
                float rec  = __shfl_xor_sync(0xffffffffu, send, 8);
                float keep = (lane & 8) ? a[i + 4] : a[i];
                a[i] = keep + rec;
            }
            #pragma unroll
            for (int i = 0; i < 2; i++) {
                float send = (lane & 4) ? a[i] : a[i + 2];
                float rec  = __shfl_xor_sync(0xffffffffu, send, 4);
                float keep = (lane & 4) ? a[i + 2] : a[i];
                a[i] = keep + rec;
            }
            {
                float send = (lane & 2) ? a[0] : a[1];
                float rec  = __shfl_xor_sync(0xffffffffu, send, 2);
                float keep = (lane & 2) ? a[1] : a[0];
                a[0] = keep + rec;
            }
            float val = a[0] + __shfl_xor_sync(0xffffffffu, a[0], 1);
            val += b_out[rowBase + rl];
            if ((lane & 1) == 0) s_log[(lane >> 1) & 15][warp * 16 + rl] = val;
        }
    }
    __syncthreads();

    // per-block exp partial sums
    {
        int bb = tid >> 4, j0 = tid & 15;
        float s = 0.f;
        #pragma unroll
        for (int j = j0; j < 128; j += 16) s += __expf(s_log[bb][j]);
        #pragma unroll
        for (int o = 8; o; o >>= 1) s += __shfl_xor_sync(0xffffffffu, s, o);
        if (j0 == 0) g_psumT[bb * 256 + blockIdx.x] = s;
    }
    __threadfence();
    if (tid == 0) s_ticket = atomicAdd(&g_ctr, 1);
    __syncthreads();

    if (s_ticket == 249) {
        for (int bb = warp; bb < BB; bb += 8) {
            float s = 0.f;
            for (int p = lane; p < 250; p += 32) s += g_psumT[bb * 256 + p];
            #pragma unroll
            for (int o = 16; o; o >>= 1) s += __shfl_xor_sync(0xffffffffu, s, o);
            if (lane == 0) g_lse[bb] = __logf(s);
        }
        __syncthreads();
        __threadfence();
        if (tid == 0) atomicExch(&g_flag, 1);
    }

    if (tid == 0) {
        volatile int* vf = &g_flag;
        while (*vf == 0) __nanosleep(64);
    }
    __syncthreads();
    __threadfence();
    if (tid < BB) s_lse[tid] = g_lse[tid];
    __syncthreads();

    // final write: out = logit - lse  (float4: 512 stores)
    const int base = blockIdx.x * 128;
    #pragma unroll
    for (int idx = tid; idx < 512; idx += 256) {
        int bb = idx >> 5, q = idx & 31;
        float4 vv = *(const float4*)(&s_log[bb][q * 4]);
        float l = s_lse[bb];
        vv.x -= l; vv.y -= l; vv.z -= l; vv.w -= l;
        *(float4*)(&out_logp[bb * VV + base + q * 4]) = vv;
    }

    __threadfence();
    if (tid == 0) {
        int d = atomicAdd(&g_done, 1);
        if (d == 249) { g_ctr = 0; g_flag = 0; g_done = 0; }
    }
}

// ============================================================================
extern "C" void kernel_launch(void* const* d_in, const int* in_sizes, int n_in,
                              void* d_out, int out_size)
{
    const float* encoder_outputs = (const float*)d_in[0];
    const int*   input_ids       = (const int*)  d_in[1];
    const float* hidden          = (const float*)d_in[2];
    const float* coverage        = (const float*)d_in[3];
    const float* emb             = (const float*)d_in[4];
    const float* W_dec           = (const float*)d_in[5];
    const float* b_dec           = (const float*)d_in[6];
    const float* attn_w          = (const float*)d_in[7];
    const float* attn_b          = (const float*)d_in[8];
    const float* cvg_w           = (const float*)d_in[9];
    const float* cvg_b           = (const float*)d_in[10];
    const float* v               = (const float*)d_in[11];
    const float* W_new           = (const float*)d_in[12];
    const float* b_new           = (const float*)d_in[13];
    const float* w_ih            = (const float*)d_in[14];
    const float* w_hh            = (const float*)d_in[15];
    const float* b_ih            = (const float*)d_in[16];
    const float* b_hh            = (const float*)d_in[17];
    const float* W_pre           = (const float*)d_in[18];
    const float* b_pre           = (const float*)d_in[19];
    const float* W_out           = (const float*)d_in[20];
    const float* b_out           = (const float*)d_in[21];

    float* out = (float*)d_out;
    float* out_logp   = out;
    float* out_hidden = out + BB * VV;
    float* out_ctx2   = out_hidden + BB * HH;
    float* out_aw2    = out_ctx2 + BB * HH;
    float* out_cov2   = out_aw2 + BB * ENCL;

    const int mma_smem = (64 * 104 + JCH * 64 * 68) * (int)sizeof(float);  // 165,888
    cudaFuncSetAttribute(k1_mma, cudaFuncAttributeMaxDynamicSharedMemorySize, mma_smem);
    const int k2_smem = 2 * ENCL * HH * (int)sizeof(float);                // 49,152
    cudaFuncSetAttribute(k2_mega, cudaFuncAttributeMaxDynamicSharedMemorySize, k2_smem);

    k1_mma<<<16 * NJC + 6, 256, mma_smem>>>(encoder_outputs, attn_w,
                                            input_ids, emb, hidden, W_dec, b_dec,
                                            coverage, cvg_w, cvg_b,
                                            w_ih, w_hh, W_new, W_pre);

    k2_mega<<<BB, 256, k2_smem>>>(encoder_outputs, coverage, hidden,
                                  W_new, b_new, w_ih, w_hh, b_ih, b_hh,
                                  W_dec, b_dec, cvg_b, v, attn_b, b_pre, W_pre,
                                  out_hidden, out_ctx2, out_aw2, out_cov2);

    k3_logits<<<250, 256>>>(W_out, b_out, out_logp);
}

// round 13
// speedup vs baseline: 1.7837x; 1.1429x over previous
#include <cuda_runtime.h>
#include <cuda_bf16.h>
#include <math.h>
#include <stdint.h>

#define BB   16
#define ENCL 64
#define HH   96
#define EE   128
#define VV   32000

#define JCH  8          // j per chunk
#define NJC  12         // j chunks (8*12 = 96)
#define NSLAB 24        // NJC * 2 k-halves

typedef unsigned long long ull;

// ---------------- scratch (device globals; no allocation allowed) ------------
__device__ float g_part[NSLAB][BB * ENCL * HH];
__device__ float g_emb[BB * EE];
__device__ float g_dec1[BB * HH];
__device__ float g_cvg1[BB * ENCL];
__device__ float g_cvgcol[ENCL * ENCL];
__device__ float g_o[BB * HH];
__device__ float g_psumT[BB * 256];
__device__ float g_lse[BB];
__device__ float g_warmsink[4 * 512];
__device__ int   g_ctr;
__device__ int   g_flag;
__device__ int   g_done;

// ---------------- helpers ---------------------------------------------------
__device__ __forceinline__ float sigmoid_fast(float x) {
    return __fdividef(1.0f, 1.0f + __expf(-x));
}
__device__ __forceinline__ float tanh_precise(float x) {
    float e = __expf(2.0f * x);
    return 1.0f - __fdividef(2.0f, e + 1.0f);
}
__device__ __forceinline__ float tanh_apx(float x) {
    float y; asm("tanh.approx.f32 %0, %1;" : "=f"(y) : "f"(x)); return y;
}
__device__ __forceinline__ uint32_t f2tf32(float x) {
    uint32_t r; asm("cvt.rna.tf32.f32 %0, %1;" : "=r"(r) : "f"(x)); return r;
}
__device__ __forceinline__ void mma_tf32(float* c,
                                         uint32_t a0, uint32_t a1, uint32_t a2, uint32_t a3,
                                         uint32_t b0, uint32_t b1) {
    asm("mma.sync.aligned.m16n8k8.row.col.f32.tf32.tf32.f32 "
        "{%0,%1,%2,%3}, {%4,%5,%6,%7}, {%8,%9}, {%0,%1,%2,%3};"
        : "+f"(c[0]), "+f"(c[1]), "+f"(c[2]), "+f"(c[3])
        : "r"(a0), "r"(a1), "r"(a2), "r"(a3), "r"(b0), "r"(b1));
}
template <int N4>
__device__ __forceinline__ float dotT(const float* __restrict__ row,
                                      const float* __restrict__ vec) {
    float a0 = 0.f, a1 = 0.f, a2 = 0.f, a3 = 0.f;
    const float4* r4 = (const float4*)row;
    #pragma unroll
    for (int q = 0; q < N4; q++) {
        float4 w = __ldg(&r4[q]);
        const float* vv = vec + q * 4;
        a0 += w.x * vv[0]; a1 += w.y * vv[1];
        a2 += w.z * vv[2]; a3 += w.w * vv[3];
    }
    return (a0 + a1) + (a2 + a3);
}

// ============================================================================
// K1: enc_feat conv partials via tf32 mma.sync + pre-work + L2 warming.
// Grid: 192 mma blocks + 2 pre + 4 warm.  **512 threads** (16 warps = 4/SMSP).
// Warps 0-7 compute k0 in [0,32), warps 8-15 k0 in [32,64); each k-half
// writes its own partial slab g_part[jc*2+khalf] (no cross-warp reduce).
// smem layout identical to R9/R12 (xs[64][104] + ws[8][64][68] = 165,888B).
// ============================================================================
__global__ void __launch_bounds__(512)
k1_mma(const float* __restrict__ enc_out,
       const float* __restrict__ attn_w,
       const int*   __restrict__ input_ids,
       const float* __restrict__ emb,
       const float* __restrict__ hidden,
       const float* __restrict__ W_dec,
       const float* __restrict__ b_dec,
       const float* __restrict__ coverage,
       const float* __restrict__ cvg_w,
       const float* __restrict__ cvg_b,
       const float* __restrict__ w_ih,
       const float* __restrict__ w_hh,
       const float* __restrict__ W_new,
       const float* __restrict__ W_pre)
{
    extern __shared__ float sm[];
    const int bid = blockIdx.x;
    const int tid = threadIdx.x;

    if (bid >= 16 * NJC) {
        if (bid == 16 * NJC) {
            for (int idx = tid; idx < BB * EE; idx += 512) {
                int b = idx >> 7, k = idx & 127;
                g_emb[idx] = emb[(long)input_ids[b] * EE + k];
            }
            float* s_hid = sm;
            for (int idx = tid; idx < BB * HH; idx += 512) s_hid[idx] = hidden[idx];
            __syncthreads();
            const int warp = tid >> 5, lane = tid & 31;
            for (int rr = warp; rr < BB * HH; rr += 16) {
                int b = rr / HH, h = rr % HH;
                const float* wr = W_dec + h * HH;
                const float* hr = s_hid + b * HH;
                float p = 0.f;
                #pragma unroll
                for (int kk = 0; kk < HH; kk += 32) p += wr[kk + lane] * hr[kk + lane];
                #pragma unroll
                for (int o = 16; o; o >>= 1) p += __shfl_xor_sync(0xffffffffu, p, o);
                if (lane == 0) g_dec1[rr] = p + b_dec[h];
            }
        } else if (bid == 16 * NJC + 1) {
            float* s_col = sm;
            float* s_cov = sm + 4096;
            for (int idx = tid; idx < ENCL * ENCL; idx += 512) {
                float val = cvg_w[idx * HH + 47];
                s_col[idx] = val;
                g_cvgcol[idx] = val;
            }
            for (int idx = tid; idx < BB * ENCL; idx += 512) s_cov[idx] = coverage[idx];
            __syncthreads();
            for (int idx = tid; idx < BB * ENCL; idx += 512) {
                int b = idx >> 6, o = idx & 63;
                float acc = cvg_b[o];
                const float* cr = s_cov + b * ENCL;
                const float* wc = s_col + o * ENCL;
                #pragma unroll 8
                for (int i = 0; i < ENCL; i++) acc += cr[i] * wc[i];
                g_cvg1[idx] = acc;
            }
        } else {
            const int wb = bid - (16 * NJC + 2);
            const float4* src = nullptr; int n4 = 0;
            if (wb == 0) { src = (const float4*)w_ih;  n4 = 288 * 24; }
            else if (wb == 1) { src = (const float4*)w_hh;  n4 = 288 * 24; }
            else if (wb == 2) { src = (const float4*)W_new; n4 = 96 * 56; }
            else { src = (const float4*)W_pre; n4 = 96 * 48; }
            float s = 0.f;
            for (int i = tid; i < n4; i += 512) {
                float4 t = __ldg(&src[i]);
                s += t.x + t.y + t.z + t.w;
            }
            if (wb == 3) {
                const float4* wd = (const float4*)W_dec;
                for (int i = tid; i < 96 * 24; i += 512) {
                    float4 t = __ldg(&wd[i]);
                    s += t.x + t.y + t.z + t.w;
                }
            }
            g_warmsink[wb * 512 + tid] = s;
        }
        return;
    }

    const int b  = bid / NJC;
    const int jc = bid % NJC;
    const int j0 = jc * JCH;

    float* xs = sm;              // [64][104]
    float* ws = sm + 64 * 104;   // [8][64][68]

    // stage x window (512-thread stride)
    for (int idx = tid; idx < 64 * 104; idx += 512) {
        int i = idx / 104, c = idx % 104;
        int xc = j0 + c - 47;
        float vv = (xc >= 0 && xc < 96) ? enc_out[(b * ENCL + i) * HH + xc] : 0.0f;
        xs[idx] = __uint_as_float(f2tf32(vv));
    }
    // stage weights: each thread handles 8 (o,i) pairs
    for (int idx = tid; idx < 4096; idx += 512) {
        int o = idx >> 6, i = idx & 63;
        const float* p = attn_w + ((size_t)(o * ENCL + i) * HH + 47) * HH + j0;
        float4 v0 = *(const float4*)(p);
        float4 v1 = *(const float4*)(p + 4);
        float* dst = ws + o * 68 + i;
        dst[0 * 4352] = __uint_as_float(f2tf32(v0.x));
        dst[1 * 4352] = __uint_as_float(f2tf32(v0.y));
        dst[2 * 4352] = __uint_as_float(f2tf32(v0.z));
        dst[3 * 4352] = __uint_as_float(f2tf32(v0.w));
        dst[4 * 4352] = __uint_as_float(f2tf32(v1.x));
        dst[5 * 4352] = __uint_as_float(f2tf32(v1.y));
        dst[6 * 4352] = __uint_as_float(f2tf32(v1.z));
        dst[7 * 4352] = __uint_as_float(f2tf32(v1.w));
    }
    __syncthreads();

    const int warp = tid >> 5, lane = tid & 31;
    const int khalf = warp >> 3;           // 0 or 1 -> k0 base 0 / 32
    const int wl  = warp & 7;
    const int o0  = (wl >> 2) * 32;
    const int w0  = (wl & 3) * 24;
    const int qr  = lane >> 2, qc = lane & 3;
    const int kbase = khalf * 32;

    float c[2][3][4];
    #pragma unroll
    for (int s = 0; s < 2; s++)
        #pragma unroll
        for (int t = 0; t < 3; t++)
            #pragma unroll
            for (int u = 0; u < 4; u++) c[s][t][u] = 0.0f;

    #pragma unroll 1
    for (int jj = 0; jj < JCH; jj++) {
        const float* wsj = ws + jj * 4352;
        const int colbase = w0 + qr + jj;
        #pragma unroll
        for (int kq = 0; kq < 32; kq += 8) {
            const int k0 = kbase + kq;
            uint32_t a[2][4];
            #pragma unroll
            for (int s = 0; s < 2; s++) {
                const float* wrow = wsj + (o0 + s * 16 + qr) * 68 + k0 + qc;
                a[s][0] = __float_as_uint(wrow[0]);
                a[s][1] = __float_as_uint(wrow[8 * 68]);
                a[s][2] = __float_as_uint(wrow[4]);
                a[s][3] = __float_as_uint(wrow[8 * 68 + 4]);
            }
            const float* xrow0 = xs + (k0 + qc) * 104 + colbase;
            const float* xrow1 = xrow0 + 4 * 104;
            #pragma unroll
            for (int t = 0; t < 3; t++) {
                uint32_t b0 = __float_as_uint(xrow0[t * 8]);
                uint32_t b1 = __float_as_uint(xrow1[t * 8]);
                mma_tf32(c[0][t], a[0][0], a[0][1], a[0][2], a[0][3], b0, b1);
                mma_tf32(c[1][t], a[1][0], a[1][1], a[1][2], a[1][3], b0, b1);
            }
        }
    }

    float* dst = g_part[jc * 2 + khalf] + b * (ENCL * HH);
    #pragma unroll
    for (int s = 0; s < 2; s++) {
        #pragma unroll
        for (int t = 0; t < 3; t++) {
            int wcol = w0 + t * 8 + 2 * qc;
            int orow = o0 + s * 16 + qr;
            *(float2*)(dst + orow * HH + wcol)       = make_float2(c[s][t][0], c[s][t][1]);
            *(float2*)(dst + (orow + 8) * HH + wcol) = make_float2(c[s][t][2], c[s][t][3]);
        }
    }
}

// ============================================================================
// K2: per-batch MEGA kernel. 16 blocks x 256.  (R12-identical except 24 slabs)
// ============================================================================
__global__ void __launch_bounds__(256, 1)
k2_mega(const float* __restrict__ enc_out,
        const float* __restrict__ coverage,
        const float* __restrict__ hidden,
        const float* __restrict__ W_new,
        const float* __restrict__ b_new,
        const float* __restrict__ w_ih,
        const float* __restrict__ w_hh,
        const float* __restrict__ b_ih,
        const float* __restrict__ b_hh,
        const float* __restrict__ W_dec,
        const float* __restrict__ b_dec,
        const float* __restrict__ cvg_b,
        const float* __restrict__ v,
        const float* __restrict__ attn_b,
        const float* __restrict__ b_pre,
        const float* __restrict__ W_pre,
        float* __restrict__ out_hidden,
        float* __restrict__ out_ctx2,
        float* __restrict__ out_aw2,
        float* __restrict__ out_cov2)
{
    extern __shared__ float dyn[];
    float* s_eo = dyn;                 // [64][96]
    float* s_ef = dyn + ENCL * HH;     // [64][96]
    __shared__ float s_h[HH], s_v[HH], s_dec[HH], s_x[HH], s_hnew[HH];
    __shared__ float s_ab[ENCL], s_cvg1[ENCL], s_cvg2[ENCL];
    __shared__ float s_aw[ENCL], s_cov1[ENCL], s_sc[ENCL];
    __shared__ __align__(16) float s_cat[EE + HH];
    __shared__ float s_gi[3 * HH], s_gh[3 * HH];

    const int b = blockIdx.x;
    const int tid = threadIdx.x;
    const int warp = tid >> 5, lane = tid & 31;

    // ---- phase 1: independent loads ----
    if (tid < 64)       s_ab[tid] = attn_b[tid];
    else if (tid < 160) s_h[tid - 64] = hidden[b * HH + tid - 64];
    else                s_v[tid - 160] = v[b * HH + tid - 160];
    if (tid < 96)       s_dec[tid] = g_dec1[b * HH + tid];
    else if (tid < 224) s_cat[tid - 96] = g_emb[b * EE + (tid - 96)];
    if (tid < 64)       s_cvg1[tid] = g_cvg1[b * ENCL + tid];

    {
        const float4* eo4 = (const float4*)(enc_out + b * ENCL * HH);
        float4* s_eo4 = (float4*)s_eo;
        float4* s_ef4 = (float4*)s_ef;
        #pragma unroll
        for (int q = 0; q < 6; q++)
            s_eo4[tid + q * 256] = __ldg(&eo4[tid + q * 256]);
        #pragma unroll
        for (int q = 0; q < 6; q++) {
            const int i4 = tid + q * 256;
            float4 acc = __ldg((const float4*)(g_part[0] + b * ENCL * HH) + i4);
            #pragma unroll
            for (int cdx = 1; cdx < NSLAB; cdx++) {
                float4 p = __ldg((const float4*)(g_part[cdx] + b * ENCL * HH) + i4);
                acc.x += p.x; acc.y += p.y; acc.z += p.z; acc.w += p.w;
            }
            s_ef4[i4] = acc;
        }
    }
    __syncthreads();

    // ---- phase 2: scores1 ----
    #pragma unroll
    for (int q = 0; q < 8; q++) {
        const int e = warp * 8 + q;
        const float cf = s_cvg1[e] + s_ab[e];
        float acc = 0.f;
        #pragma unroll
        for (int kk = 0; kk < HH; kk += 32) {
            int h = kk + lane;
            acc += tanh_apx(s_ef[e * HH + h] + s_dec[h] + cf) * s_v[h];
        }
        #pragma unroll
        for (int o = 16; o; o >>= 1) acc += __shfl_xor_sync(0xffffffffu, acc, o);
        if (lane == 0) s_sc[e] = acc;
    }
    __syncthreads();

    // ---- phase 3: warp7 softmax1; warps 0-6 compute gh ----
    if (warp == 7) {
        float a0 = s_sc[lane], a1 = s_sc[lane + 32];
        float m = fmaxf(a0, a1);
        #pragma unroll
        for (int o = 16; o; o >>= 1) m = fmaxf(m, __shfl_xor_sync(0xffffffffu, m, o));
        float e0 = __expf(a0 - m), e1 = __expf(a1 - m);
        float s = e0 + e1;
        #pragma unroll
        for (int o = 16; o; o >>= 1) s += __shfl_xor_sync(0xffffffffu, s, o);
        float inv = __fdividef(1.0f, s);
        s_aw[lane] = e0 * inv; s_aw[lane + 32] = e1 * inv;
    } else {
        int rr = warp * 32 + lane;
        s_gh[rr] = dotT<24>(w_hh + rr * HH, s_h) + b_hh[rr];
        if (rr < 64) {
            int r2 = 224 + rr;
            s_gh[r2] = dotT<24>(w_hh + r2 * HH, s_h) + b_hh[r2];
        }
    }
    __syncthreads();

    // ---- phase 4: cov1 + ctx1 ----
    if (tid < ENCL) s_cov1[tid] = coverage[b * ENCL + tid] + s_aw[tid];
    if (tid < HH) {
        float acc = 0.f;
        #pragma unroll 8
        for (int e = 0; e < ENCL; e++) acc += s_aw[e] * s_eo[e * HH + tid];
        s_cat[EE + tid] = acc;
    }
    __syncthreads();

    // ---- phase 5: x ----
    if (tid < HH) s_x[tid] = dotT<56>(W_new + tid * (EE + HH), s_cat) + b_new[tid];
    __syncthreads();

    // ---- phase 6: gi ----
    s_gi[tid] = dotT<24>(w_ih + tid * HH, s_x) + b_ih[tid];
    if (tid < 32) {
        int r2 = 256 + tid;
        s_gi[r2] = dotT<24>(w_ih + r2 * HH, s_x) + b_ih[r2];
    }
    __syncthreads();

    // ---- phase 7: gates ----
    if (tid < HH) {
        float r = sigmoid_fast(s_gi[tid] + s_gh[tid]);
        float z = sigmoid_fast(s_gi[HH + tid] + s_gh[HH + tid]);
        float n = tanh_precise(s_gi[2 * HH + tid] + r * s_gh[2 * HH + tid]);
        float hn = (1.0f - z) * n + z * s_h[tid];
        s_hnew[tid] = hn;
        s_cat[tid] = hn;
        out_hidden[b * HH + tid] = hn;
    }
    __syncthreads();

    // ---- phase 8: dec2 + cvg2 ----
    if (tid < HH) {
        s_dec[tid] = dotT<24>(W_dec + tid * HH, s_hnew) + b_dec[tid];
    } else if (tid < HH + ENCL) {
        const int o = tid - HH;
        s_cvg2[o] = dotT<16>(g_cvgcol + o * ENCL, s_cov1) + cvg_b[o];
    }
    __syncthreads();

    // ---- phase 9: scores2 ----
    #pragma unroll
    for (int q = 0; q < 8; q++) {
        const int e = warp * 8 + q;
        const float cf = s_cvg2[e] + s_ab[e];
        float acc = 0.f;
        #pragma unroll
        for (int kk = 0; kk < HH; kk += 32) {
            int h = kk + lane;
            acc += tanh_apx(s_ef[e * HH + h] + s_dec[h] + cf) * s_v[h];
        }
        #pragma unroll
        for (int o = 16; o; o >>= 1) acc += __shfl_xor_sync(0xffffffffu, acc, o);
        if (lane == 0) s_sc[e] = acc;
    }
    __syncthreads();

    // ---- phase 10: softmax2 ----
    if (warp == 7) {
        float a0 = s_sc[lane], a1 = s_sc[lane + 32];
        float m = fmaxf(a0, a1);
        #pragma unroll
        for (int o = 16; o; o >>= 1) m = fmaxf(m, __shfl_xor_sync(0xffffffffu, m, o));
        float e0 = __expf(a0 - m), e1 = __expf(a1 - m);
        float s = e0 + e1;
        #pragma unroll
        for (int o = 16; o; o >>= 1) s += __shfl_xor_sync(0xffffffffu, s, o);
        float inv = __fdividef(1.0f, s);
        s_aw[lane] = e0 * inv; s_aw[lane + 32] = e1 * inv;
    }
    __syncthreads();

    // ---- phase 11: outputs + ctx2 ----
    if (tid < ENCL) {
        float aw = s_aw[tid];
        out_aw2[b * ENCL + tid] = aw;
        out_cov2[b * ENCL + tid] = s_cov1[tid] + aw;
    }
    if (tid < HH) {
        float acc = 0.f;
        #pragma unroll 8
        for (int e = 0; e < ENCL; e++) acc += s_aw[e] * s_eo[e * HH + tid];
        s_cat[HH + tid] = acc;
        out_ctx2[b * HH + tid] = acc;
    }
    __syncthreads();

    // ---- phase 12: o ----
    if (tid < HH)
        g_o[b * HH + tid] = tanh_precise(
            dotT<48>(W_pre + tid * (2 * HH), s_cat) + b_pre[tid]);
}

// ============================================================================
// K3: logits + fused log_softmax finalize.  (R12-identical)
// ============================================================================
__global__ void __launch_bounds__(256, 2)
k3_logits(const float* __restrict__ W_out, const float* __restrict__ b_out,
          float* __restrict__ out_logp)
{
    __shared__ float s_so[HH][BB];
    __shared__ __align__(16) float s_log[BB][132];
    __shared__ float s_lse[BB];
    __shared__ int   s_ticket;
    const int tid = threadIdx.x, warp = tid >> 5, lane = tid & 31;

    for (int idx = tid; idx < BB * HH; idx += 256) {
        int bb = idx / HH, h = idx % HH;
        s_so[h][bb] = g_o[idx];
    }
    __syncthreads();

    float sA[16], sB[16], sC[16];
    #pragma unroll
    for (int q = 0; q < 4; q++) {
        float4 t0 = ((const float4*)s_so[lane])[q];
        float4 t1 = ((const float4*)s_so[lane + 32])[q];
        float4 t2 = ((const float4*)s_so[lane + 64])[q];
        sA[q*4+0]=t0.x; sA[q*4+1]=t0.y; sA[q*4+2]=t0.z; sA[q*4+3]=t0.w;
        sB[q*4+0]=t1.x; sB[q*4+1]=t1.y; sB[q*4+2]=t1.z; sB[q*4+3]=t1.w;
        sC[q*4+0]=t2.x; sC[q*4+1]=t2.y; sC[q*4+2]=t2.z; sC[q*4+3]=t2.w;
    }

    const int rowBase = blockIdx.x * 128 + warp * 16;

    float p0[4], p1[4], p2[4];
    #pragma unroll
    for (int r = 0; r < 4; r++) {
        const float* wr = W_out + (size_t)(rowBase + r) * HH;
        p0[r] = __ldg(wr + lane);
        p1[r] = __ldg(wr + lane + 32);
        p2[r] = __ldg(wr + lane + 64);
    }

    #pragma unroll
    for (int g = 0; g < 4; g++) {
        #pragma unroll
        for (int r = 0; r < 4; r++) {
            float cw0 = p0[r], cw1 = p1[r], cw2 = p2[r];
            if (g < 3) {
                const float* wr = W_out + (size_t)(rowBase + (g + 1) * 4 + r) * HH;
                p0[r] = __ldg(wr + lane);
                p1[r] = __ldg(wr + lane + 32);
                p2[r] = __ldg(wr + lane + 64);
            }
            const int rl = g * 4 + r;

            float a[16];
            #pragma unroll
            for (int bb = 0; bb < 16; bb++) a[bb] = cw0 * sA[bb] + cw1 * sB[bb] + cw2 * sC[bb];

            #pragma unroll
            for (int i = 0; i < 8; i++) {
                float send = (lane & 16) ? a[i] : a[i + 8];
                float rec  = __shfl_xor_sync(0xffffffffu, send, 16);
                float keep = (lane & 16) ? a[i + 8] : a[i];
                a[i] = keep + rec;
            }
            #pragma unroll
            for (int i = 0; i < 4; i++) {
                float send = (lane & 8) ? a[i] : a[i + 4];
                float rec  = __shfl_xor_sync(0xffffffffu, send, 8);
                float keep = (lane & 8) ? a[i + 4] : a[i];
                a[i] = keep + rec;
            }
            #pragma unroll
            for (int i = 0; i < 2; i++) {
                float send = (lane & 4) ? a[i] : a[i + 2];
                float rec  = __shfl_xor_sync(0xffffffffu, send, 4);
                float keep = (lane & 4) ? a[i + 2] : a[i];
                a[i] = keep + rec;
            }
            {
                float send = (lane & 2) ? a[0] : a[1];
                float rec  = __shfl_xor_sync(0xffffffffu, send, 2);
                float keep = (lane & 2) ? a[1] : a[0];
                a[0] = keep + rec;
            }
            float val = a[0] + __shfl_xor_sync(0xffffffffu, a[0], 1);
            val += b_out[rowBase + rl];
            if ((lane & 1) == 0) s_log[(lane >> 1) & 15][warp * 16 + rl] = val;
        }
    }
    __syncthreads();

    {
        int bb = tid >> 4, j0 = tid & 15;
        float s = 0.f;
        #pragma unroll
        for (int j = j0; j < 128; j += 16) s += __expf(s_log[bb][j]);
        #pragma unroll
        for (int o = 8; o; o >>= 1) s += __shfl_xor_sync(0xffffffffu, s, o);
        if (j0 == 0) g_psumT[bb * 256 + blockIdx.x] = s;
    }
    __threadfence();
    if (tid == 0) s_ticket = atomicAdd(&g_ctr, 1);
    __syncthreads();

    if (s_ticket == 249) {
        for (int bb = warp; bb < BB; bb += 8) {
            float s = 0.f;
            for (int p = lane; p < 250; p += 32) s += g_psumT[bb * 256 + p];
            #pragma unroll
            for (int o = 16; o; o >>= 1) s += __shfl_xor_sync(0xffffffffu, s, o);
            if (lane == 0) g_lse[bb] = __logf(s);
        }
        __syncthreads();
        __threadfence();
        if (tid == 0) atomicExch(&g_flag, 1);
    }

    if (tid == 0) {
        volatile int* vf = &g_flag;
        while (*vf == 0) __nanosleep(64);
    }
    __syncthreads();
    __threadfence();
    if (tid < BB) s_lse[tid] = g_lse[tid];
    __syncthreads();

    const int base = blockIdx.x * 128;
    #pragma unroll
    for (int idx = tid; idx < 512; idx += 256) {
        int bb = idx >> 5, q = idx & 31;
        float4 vv = *(const float4*)(&s_log[bb][q * 4]);
        float l = s_lse[bb];
        vv.x -= l; vv.y -= l; vv.z -= l; vv.w -= l;
        *(float4*)(&out_logp[bb * VV + base + q * 4]) = vv;
    }

    __threadfence();
    if (tid == 0) {
        int d = atomicAdd(&g_done, 1);
        if (d == 249) { g_ctr = 0; g_flag = 0; g_done = 0; }
    }
}

// ============================================================================
extern "C" void kernel_launch(void* const* d_in, const int* in_sizes, int n_in,
                              void* d_out, int out_size)
{
    const float* encoder_outputs = (const float*)d_in[0];
    const int*   input_ids       = (const int*)  d_in[1];
    const float* hidden          = (const float*)d_in[2];
    const float* coverage        = (const float*)d_in[3];
    const float* emb             = (const float*)d_in[4];
    const float* W_dec           = (const float*)d_in[5];
    const float* b_dec           = (const float*)d_in[6];
    const float* attn_w          = (const float*)d_in[7];
    const float* attn_b          = (const float*)d_in[8];
    const float* cvg_w           = (const float*)d_in[9];
    const float* cvg_b           = (const float*)d_in[10];
    const float* v               = (const float*)d_in[11];
    const float* W_new           = (const float*)d_in[12];
    const float* b_new           = (const float*)d_in[13];
    const float* w_ih            = (const float*)d_in[14];
    const float* w_hh            = (const float*)d_in[15];
    const float* b_ih            = (const float*)d_in[16];
    const float* b_hh            = (const float*)d_in[17];
    const float* W_pre           = (const float*)d_in[18];
    const float* b_pre           = (const float*)d_in[19];
    const float* W_out           = (const float*)d_in[20];
    const float* b_out           = (const float*)d_in[21];

    float* out = (float*)d_out;
    float* out_logp   = out;
    float* out_hidden = out + BB * VV;
    float* out_ctx2   = out_hidden + BB * HH;
    float* out_aw2    = out_ctx2 + BB * HH;
    float* out_cov2   = out_aw2 + BB * ENCL;

    const int mma_smem = (64 * 104 + JCH * 64 * 68) * (int)sizeof(float);  // 165,888
    cudaFuncSetAttribute(k1_mma, cudaFuncAttributeMaxDynamicSharedMemorySize, mma_smem);
    const int k2_smem = 2 * ENCL * HH * (int)sizeof(float);                // 49,152
    cudaFuncSetAttribute(k2_mega, cudaFuncAttributeMaxDynamicSharedMemorySize, k2_smem);

    k1_mma<<<16 * NJC + 6, 512, mma_smem>>>(encoder_outputs, attn_w,
                                            input_ids, emb, hidden, W_dec, b_dec,
                                            coverage, cvg_w, cvg_b,
                                            w_ih, w_hh, W_new, W_pre);

    k2_mega<<<BB, 256, k2_smem>>>(encoder_outputs, coverage, hidden,
                                  W_new, b_new, w_ih, w_hh, b_ih, b_hh,
                                  W_dec, b_dec, cvg_b, v, attn_b, b_pre, W_pre,
                                  out_hidden, out_ctx2, out_aw2, out_cov2);

    k3_logits<<<250, 256>>>(W_out, b_out, out_logp);
}

// round 15
// speedup vs baseline: 2.0516x; 1.1502x over previous
#include <cuda_runtime.h>
#include <cuda_bf16.h>
#include <math.h>
#include <stdint.h>

#define BB   16
#define ENCL 64
#define HH   96
#define EE   128
#define VV   32000

#define JCH  8          // j per chunk
#define NJC  12         // j chunks (8*12 = 96) == slab count

typedef unsigned long long ull;

// ---------------- scratch (device globals; no allocation allowed) ------------
__device__ float g_part[NJC][BB * ENCL * HH];
__device__ float g_emb[BB * EE];
__device__ float g_dec1[BB * HH];
__device__ float g_cvg1[BB * ENCL];
__device__ float g_cvgcol[ENCL * ENCL];
__device__ float g_o[BB * HH];
__device__ float g_psumT[BB * 256];
__device__ float g_lse[BB];
__device__ float g_warmsink[4 * 1024];
__device__ int   g_ctr;
__device__ int   g_flag;
__device__ int   g_done;

// ---------------- helpers ---------------------------------------------------
__device__ __forceinline__ float sigmoid_fast(float x) {
    return __fdividef(1.0f, 1.0f + __expf(-x));
}
__device__ __forceinline__ float tanh_precise(float x) {
    float e = __expf(2.0f * x);
    return 1.0f - __fdividef(2.0f, e + 1.0f);
}
__device__ __forceinline__ float tanh_apx(float x) {
    float y; asm("tanh.approx.f32 %0, %1;" : "=f"(y) : "f"(x)); return y;
}
__device__ __forceinline__ uint32_t f2tf32(float x) {
    uint32_t r; asm("cvt.rna.tf32.f32 %0, %1;" : "=r"(r) : "f"(x)); return r;
}
__device__ __forceinline__ void mma_tf32(float* c,
                                         uint32_t a0, uint32_t a1, uint32_t a2, uint32_t a3,
                                         uint32_t b0, uint32_t b1) {
    asm("mma.sync.aligned.m16n8k8.row.col.f32.tf32.tf32.f32 "
        "{%0,%1,%2,%3}, {%4,%5,%6,%7}, {%8,%9}, {%0,%1,%2,%3};"
        : "+f"(c[0]), "+f"(c[1]), "+f"(c[2]), "+f"(c[3])
        : "r"(a0), "r"(a1), "r"(a2), "r"(a3), "r"(b0), "r"(b1));
}
template <int N4>
__device__ __forceinline__ float dotT(const float* __restrict__ row,
                                      const float* __restrict__ vec) {
    float a0 = 0.f, a1 = 0.f, a2 = 0.f, a3 = 0.f;
    const float4* r4 = (const float4*)row;
    #pragma unroll
    for (int q = 0; q < N4; q++) {
        float4 w = __ldg(&r4[q]);
        const float* vv = vec + q * 4;
        a0 += w.x * vv[0]; a1 += w.y * vv[1];
        a2 += w.z * vv[2]; a3 += w.w * vv[3];
    }
    return (a0 + a1) + (a2 + a3);
}

// ============================================================================
// K1: enc_feat conv partials via tf32 mma.sync + pre-work + L2 warming.
// Grid: 192 mma blocks + 2 pre + 4 warm.  **1024 threads** (32 warps, 8/SMSP).
// Warp w: kq = w>>3 covers k in [kq*16, kq*16+16); quarters 1-3 stage their
// accumulators to smem (dead ws region) and quarter 0 reduces -> 12 slabs.
// smem: xs[64][104] + ws[8][64][68] = 165,888B (1 block/SM).
// ============================================================================
__global__ void __launch_bounds__(1024)
k1_mma(const float* __restrict__ enc_out,
       const float* __restrict__ attn_w,
       const int*   __restrict__ input_ids,
       const float* __restrict__ emb,
       const float* __restrict__ hidden,
       const float* __restrict__ W_dec,
       const float* __restrict__ b_dec,
       const float* __restrict__ coverage,
       const float* __restrict__ cvg_w,
       const float* __restrict__ cvg_b,
       const float* __restrict__ w_ih,
       const float* __restrict__ w_hh,
       const float* __restrict__ W_new,
       const float* __restrict__ W_pre)
{
    extern __shared__ float sm[];
    const int bid = blockIdx.x;
    const int tid = threadIdx.x;

    if (bid >= 16 * NJC) {
        if (bid == 16 * NJC) {
            for (int idx = tid; idx < BB * EE; idx += 1024) {
                int b = idx >> 7, k = idx & 127;
                g_emb[idx] = emb[(long)input_ids[b] * EE + k];
            }
            float* s_hid = sm;
            for (int idx = tid; idx < BB * HH; idx += 1024) s_hid[idx] = hidden[idx];
            __syncthreads();
            const int warp = tid >> 5, lane = tid & 31;
            for (int rr = warp; rr < BB * HH; rr += 32) {
                int b = rr / HH, h = rr % HH;
                const float* wr = W_dec + h * HH;
                const float* hr = s_hid + b * HH;
                float p = 0.f;
                #pragma unroll
                for (int kk = 0; kk < HH; kk += 32) p += wr[kk + lane] * hr[kk + lane];
                #pragma unroll
                for (int o = 16; o; o >>= 1) p += __shfl_xor_sync(0xffffffffu, p, o);
                if (lane == 0) g_dec1[rr] = p + b_dec[h];
            }
        } else if (bid == 16 * NJC + 1) {
            float* s_col = sm;
            float* s_cov = sm + 4096;
            for (int idx = tid; idx < ENCL * ENCL; idx += 1024) {
                float val = cvg_w[idx * HH + 47];
                s_col[idx] = val;
                g_cvgcol[idx] = val;
            }
            for (int idx = tid; idx < BB * ENCL; idx += 1024) s_cov[idx] = coverage[idx];
            __syncthreads();
            for (int idx = tid; idx < BB * ENCL; idx += 1024) {
                int b = idx >> 6, o = idx & 63;
                float acc = cvg_b[o];
                const float* cr = s_cov + b * ENCL;
                const float* wc = s_col + o * ENCL;
                #pragma unroll 8
                for (int i = 0; i < ENCL; i++) acc += cr[i] * wc[i];
                g_cvg1[idx] = acc;
            }
        } else {
            const int wb = bid - (16 * NJC + 2);
            const float4* src = nullptr; int n4 = 0;
            if (wb == 0) { src = (const float4*)w_ih;  n4 = 288 * 24; }
            else if (wb == 1) { src = (const float4*)w_hh;  n4 = 288 * 24; }
            else if (wb == 2) { src = (const float4*)W_new; n4 = 96 * 56; }
            else { src = (const float4*)W_pre; n4 = 96 * 48; }
            float s = 0.f;
            for (int i = tid; i < n4; i += 1024) {
                float4 t = __ldg(&src[i]);
                s += t.x + t.y + t.z + t.w;
            }
            if (wb == 3) {
                const float4* wd = (const float4*)W_dec;
                for (int i = tid; i < 96 * 24; i += 1024) {
                    float4 t = __ldg(&wd[i]);
                    s += t.x + t.y + t.z + t.w;
                }
            }
            g_warmsink[wb * 1024 + tid] = s;
        }
        return;
    }

    const int b  = bid / NJC;
    const int jc = bid % NJC;
    const int j0 = jc * JCH;

    float* xs = sm;              // [64][104]
    float* ws = sm + 64 * 104;   // [8][64][68]

    // stage x window
    for (int idx = tid; idx < 64 * 104; idx += 1024) {
        int i = idx / 104, c = idx % 104;
        int xc = j0 + c - 47;
        float vv = (xc >= 0 && xc < 96) ? enc_out[(b * ENCL + i) * HH + xc] : 0.0f;
        xs[idx] = __uint_as_float(f2tf32(vv));
    }
    // stage weights
    for (int idx = tid; idx < 4096; idx += 1024) {
        int o = idx >> 6, i = idx & 63;
        const float* p = attn_w + ((size_t)(o * ENCL + i) * HH + 47) * HH + j0;
        float4 v0 = *(const float4*)(p);
        float4 v1 = *(const float4*)(p + 4);
        float* dst = ws + o * 68 + i;
        dst[0 * 4352] = __uint_as_float(f2tf32(v0.x));
        dst[1 * 4352] = __uint_as_float(f2tf32(v0.y));
        dst[2 * 4352] = __uint_as_float(f2tf32(v0.z));
        dst[3 * 4352] = __uint_as_float(f2tf32(v0.w));
        dst[4 * 4352] = __uint_as_float(f2tf32(v1.x));
        dst[5 * 4352] = __uint_as_float(f2tf32(v1.y));
        dst[6 * 4352] = __uint_as_float(f2tf32(v1.z));
        dst[7 * 4352] = __uint_as_float(f2tf32(v1.w));
    }
    __syncthreads();

    const int warp = tid >> 5, lane = tid & 31;
    const int kq  = warp >> 3;             // 0..3 -> k base 0/16/32/48
    const int wl  = warp & 7;
    const int o0  = (wl >> 2) * 32;
    const int w0  = (wl & 3) * 24;
    const int qr  = lane >> 2, qc = lane & 3;
    const int kbase = kq * 16;

    float c[2][3][4];
    #pragma unroll
    for (int s = 0; s < 2; s++)
        #pragma unroll
        for (int t = 0; t < 3; t++)
            #pragma unroll
            for (int u = 0; u < 4; u++) c[s][t][u] = 0.0f;

    #pragma unroll 1
    for (int jj = 0; jj < JCH; jj++) {
        const float* wsj = ws + jj * 4352;
        const int colbase = w0 + qr + jj;
        #pragma unroll
        for (int ks = 0; ks < 16; ks += 8) {
            const int k0 = kbase + ks;
            uint32_t a[2][4];
            #pragma unroll
            for (int s = 0; s < 2; s++) {
                const float* wrow = wsj + (o0 + s * 16 + qr) * 68 + k0 + qc;
                a[s][0] = __float_as_uint(wrow[0]);
                a[s][1] = __float_as_uint(wrow[8 * 68]);
                a[s][2] = __float_as_uint(wrow[4]);
                a[s][3] = __float_as_uint(wrow[8 * 68 + 4]);
            }
            const float* xrow0 = xs + (k0 + qc) * 104 + colbase;
            const float* xrow1 = xrow0 + 4 * 104;
            #pragma unroll
            for (int t = 0; t < 3; t++) {
                uint32_t b0 = __float_as_uint(xrow0[t * 8]);
                uint32_t b1 = __float_as_uint(xrow1[t * 8]);
                mma_tf32(c[0][t], a[0][0], a[0][1], a[0][2], a[0][3], b0, b1);
                mma_tf32(c[1][t], a[1][0], a[1][1], a[1][2], a[1][3], b0, b1);
            }
        }
    }

    // ---- in-block reduction over the 4 k-quarters -> single slab ----
    // quarters 1..3 stage 24 floats/lane into dead ws region (stride-25 rows)
    __syncthreads();                      // all mainloop smem reads done
    float* rbuf = ws;                     // 24 rows x 800 floats = 76,800B
    if (kq > 0) {
        float* dstr = rbuf + ((kq - 1) * 8 + wl) * 800 + lane * 25;
        #pragma unroll
        for (int s = 0; s < 2; s++)
            #pragma unroll
            for (int t = 0; t < 3; t++) {
                dstr[s * 12 + t * 4 + 0] = c[s][t][0];
                dstr[s * 12 + t * 4 + 1] = c[s][t][1];
                dstr[s * 12 + t * 4 + 2] = c[s][t][2];
                dstr[s * 12 + t * 4 + 3] = c[s][t][3];
            }
    }
    __syncthreads();

    if (kq == 0) {
        #pragma unroll
        for (int r = 0; r < 3; r++) {
            const float* srcr = rbuf + (r * 8 + wl) * 800 + lane * 25;
            #pragma unroll
            for (int s = 0; s < 2; s++)
                #pragma unroll
                for (int t = 0; t < 3; t++) {
                    c[s][t][0] += srcr[s * 12 + t * 4 + 0];
                    c[s][t][1] += srcr[s * 12 + t * 4 + 1];
                    c[s][t][2] += srcr[s * 12 + t * 4 + 2];
                    c[s][t][3] += srcr[s * 12 + t * 4 + 3];
                }
        }
        float* dst = g_part[jc] + b * (ENCL * HH);
        #pragma unroll
        for (int s = 0; s < 2; s++) {
            #pragma unroll
            for (int t = 0; t < 3; t++) {
                int wcol = w0 + t * 8 + 2 * qc;
                int orow = o0 + s * 16 + qr;
                *(float2*)(dst + orow * HH + wcol)       = make_float2(c[s][t][0], c[s][t][1]);
                *(float2*)(dst + (orow + 8) * HH + wcol) = make_float2(c[s][t][2], c[s][t][3]);
            }
        }
    }
}

// ============================================================================
// K2: per-batch MEGA kernel. 16 blocks x 256.  (12 slabs)
// ============================================================================
__global__ void __launch_bounds__(256, 1)
k2_mega(const float* __restrict__ enc_out,
        const float* __restrict__ coverage,
        const float* __restrict__ hidden,
        const float* __restrict__ W_new,
        const float* __restrict__ b_new,
        const float* __restrict__ w_ih,
        const float* __restrict__ w_hh,
        const float* __restrict__ b_ih,
        const float* __restrict__ b_hh,
        const float* __restrict__ W_dec,
        const float* __restrict__ b_dec,
        const float* __restrict__ cvg_b,
        const float* __restrict__ v,
        const float* __restrict__ attn_b,
        const float* __restrict__ b_pre,
        const float* __restrict__ W_pre,
        float* __restrict__ out_hidden,
        float* __restrict__ out_ctx2,
        float* __restrict__ out_aw2,
        float* __restrict__ out_cov2)
{
    extern __shared__ float dyn[];
    float* s_eo = dyn;                 // [64][96]
    float* s_ef = dyn + ENCL * HH;     // [64][96]
    __shared__ float s_h[HH], s_v[HH], s_dec[HH], s_x[HH], s_hnew[HH];
    __shared__ float s_ab[ENCL], s_cvg1[ENCL], s_cvg2[ENCL];
    __shared__ float s_aw[ENCL], s_cov1[ENCL], s_sc[ENCL];
    __shared__ __align__(16) float s_cat[EE + HH];
    __shared__ float s_gi[3 * HH], s_gh[3 * HH];

    const int b = blockIdx.x;
    const int tid = threadIdx.x;
    const int warp = tid >> 5, lane = tid & 31;

    // ---- phase 1: independent loads ----
    if (tid < 64)       s_ab[tid] = attn_b[tid];
    else if (tid < 160) s_h[tid - 64] = hidden[b * HH + tid - 64];
    else                s_v[tid - 160] = v[b * HH + tid - 160];
    if (tid < 96)       s_dec[tid] = g_dec1[b * HH + tid];
    else if (tid < 224) s_cat[tid - 96] = g_emb[b * EE + (tid - 96)];
    if (tid < 64)       s_cvg1[tid] = g_cvg1[b * ENCL + tid];

    {
        const float4* eo4 = (const float4*)(enc_out + b * ENCL * HH);
        float4* s_eo4 = (float4*)s_eo;
        float4* s_ef4 = (float4*)s_ef;
        #pragma unroll
        for (int q = 0; q < 6; q++)
            s_eo4[tid + q * 256] = __ldg(&eo4[tid + q * 256]);
        #pragma unroll
        for (int q = 0; q < 6; q++) {
            const int i4 = tid + q * 256;
            float4 acc = __ldg((const float4*)(g_part[0] + b * ENCL * HH) + i4);
            #pragma unroll
            for (int cdx = 1; cdx < NJC; cdx++) {
                float4 p = __ldg((const float4*)(g_part[cdx] + b * ENCL * HH) + i4);
                acc.x += p.x; acc.y += p.y; acc.z += p.z; acc.w += p.w;
            }
            s_ef4[i4] = acc;
        }
    }
    __syncthreads();

    // ---- phase 2: scores1 ----
    #pragma unroll
    for (int q = 0; q < 8; q++) {
        const int e = warp * 8 + q;
        const float cf = s_cvg1[e] + s_ab[e];
        float acc = 0.f;
        #pragma unroll
        for (int kk = 0; kk < HH; kk += 32) {
            int h = kk + lane;
            acc += tanh_apx(s_ef[e * HH + h] + s_dec[h] + cf) * s_v[h];
        }
        #pragma unroll
        for (int o = 16; o; o >>= 1) acc += __shfl_xor_sync(0xffffffffu, acc, o);
        if (lane == 0) s_sc[e] = acc;
    }
    __syncthreads();

    // ---- phase 3: warp7 softmax1; warps 0-6 compute gh ----
    if (warp == 7) {
        float a0 = s_sc[lane], a1 = s_sc[lane + 32];
        float m = fmaxf(a0, a1);
        #pragma unroll
        for (int o = 16; o; o >>= 1) m = fmaxf(m, __shfl_xor_sync(0xffffffffu, m, o));
        float e0 = __expf(a0 - m), e1 = __expf(a1 - m);
        float s = e0 + e1;
        #pragma unroll
        for (int o = 16; o; o >>= 1) s += __shfl_xor_sync(0xffffffffu, s, o);
        float inv = __fdividef(1.0f, s);
        s_aw[lane] = e0 * inv; s_aw[lane + 32] = e1 * inv;
    } else {
        int rr = warp * 32 + lane;
        s_gh[rr] = dotT<24>(w_hh + rr * HH, s_h) + b_hh[rr];
        if (rr < 64) {
            int r2 = 224 + rr;
            s_gh[r2] = dotT<24>(w_hh + r2 * HH, s_h) + b_hh[r2];
        }
    }
    __syncthreads();

    // ---- phase 4: cov1 + ctx1 ----
    if (tid < ENCL) s_cov1[tid] = coverage[b * ENCL + tid] + s_aw[tid];
    if (tid < HH) {
        float acc = 0.f;
        #pragma unroll 8
        for (int e = 0; e < ENCL; e++) acc += s_aw[e] * s_eo[e * HH + tid];
        s_cat[EE + tid] = acc;
    }
    __syncthreads();

    // ---- phase 5: x ----
    if (tid < HH) s_x[tid] = dotT<56>(W_new + tid * (EE + HH), s_cat) + b_new[tid];
    __syncthreads();

    // ---- phase 6: gi ----
    s_gi[tid] = dotT<24>(w_ih + tid * HH, s_x) + b_ih[tid];
    if (tid < 32) {
        int r2 = 256 + tid;
        s_gi[r2] = dotT<24>(w_ih + r2 * HH, s_x) + b_ih[r2];
    }
    __syncthreads();

    // ---- phase 7: gates ----
    if (tid < HH) {
        float r = sigmoid_fast(s_gi[tid] + s_gh[tid]);
        float z = sigmoid_fast(s_gi[HH + tid] + s_gh[HH + tid]);
        float n = tanh_precise(s_gi[2 * HH + tid] + r * s_gh[2 * HH + tid]);
        float hn = (1.0f - z) * n + z * s_h[tid];
        s_hnew[tid] = hn;
        s_cat[tid] = hn;
        out_hidden[b * HH + tid] = hn;
    }
    __syncthreads();

    // ---- phase 8: dec2 + cvg2 ----
    if (tid < HH) {
        s_dec[tid] = dotT<24>(W_dec + tid * HH, s_hnew) + b_dec[tid];
    } else if (tid < HH + ENCL) {
        const int o = tid - HH;
        s_cvg2[o] = dotT<16>(g_cvgcol + o * ENCL, s_cov1) + cvg_b[o];
    }
    __syncthreads();

    // ---- phase 9: scores2 ----
    #pragma unroll
    for (int q = 0; q < 8; q++) {
        const int e = warp * 8 + q;
        const float cf = s_cvg2[e] + s_ab[e];
        float acc = 0.f;
        #pragma unroll
        for (int kk = 0; kk < HH; kk += 32) {
            int h = kk + lane;
            acc += tanh_apx(s_ef[e * HH + h] + s_dec[h] + cf) * s_v[h];
        }
        #pragma unroll
        for (int o = 16; o; o >>= 1) acc += __shfl_xor_sync(0xffffffffu, acc, o);
        if (lane == 0) s_sc[e] = acc;
    }
    __syncthreads();

    // ---- phase 10: softmax2 ----
    if (warp == 7) {
        float a0 = s_sc[lane], a1 = s_sc[lane + 32];
        float m = fmaxf(a0, a1);
        #pragma unroll
        for (int o = 16; o; o >>= 1) m = fmaxf(m, __shfl_xor_sync(0xffffffffu, m, o));
        float e0 = __expf(a0 - m), e1 = __expf(a1 - m);
        float s = e0 + e1;
        #pragma unroll
        for (int o = 16; o; o >>= 1) s += __shfl_xor_sync(0xffffffffu, s, o);
        float inv = __fdividef(1.0f, s);
        s_aw[lane] = e0 * inv; s_aw[lane + 32] = e1 * inv;
    }
    __syncthreads();

    // ---- phase 11: outputs + ctx2 ----
    if (tid < ENCL) {
        float aw = s_aw[tid];
        out_aw2[b * ENCL + tid] = aw;
        out_cov2[b * ENCL + tid] = s_cov1[tid] + aw;
    }
    if (tid < HH) {
        float acc = 0.f;
        #pragma unroll 8
        for (int e = 0; e < ENCL; e++) acc += s_aw[e] * s_eo[e * HH + tid];
        s_cat[HH + tid] = acc;
        out_ctx2[b * HH + tid] = acc;
    }
    __syncthreads();

    // ---- phase 12: o ----
    if (tid < HH)
        g_o[b * HH + tid] = tanh_precise(
            dotT<48>(W_pre + tid * (2 * HH), s_cat) + b_pre[tid]);
}

// ============================================================================
// K3: logits + fused log_softmax finalize.  (R12-identical)
// ============================================================================
__global__ void __launch_bounds__(256, 2)
k3_logits(const float* __restrict__ W_out, const float* __restrict__ b_out,
          float* __restrict__ out_logp)
{
    __shared__ float s_so[HH][BB];
    __shared__ __align__(16) float s_log[BB][132];
    __shared__ float s_lse[BB];
    __shared__ int   s_ticket;
    const int tid = threadIdx.x, warp = tid >> 5, lane = tid & 31;

    for (int idx = tid; idx < BB * HH; idx += 256) {
        int bb = idx / HH, h = idx % HH;
        s_so[h][bb] = g_o[idx];
    }
    __syncthreads();

    float sA[16], sB[16], sC[16];
    #pragma unroll
    for (int q = 0; q < 4; q++) {
        float4 t0 = ((const float4*)s_so[lane])[q];
        float4 t1 = ((const float4*)s_so[lane + 32])[q];
        float4 t2 = ((const float4*)s_so[lane + 64])[q];
        sA[q*4+0]=t0.x; sA[q*4+1]=t0.y; sA[q*4+2]=t0.z; sA[q*4+3]=t0.w;
        sB[q*4+0]=t1.x; sB[q*4+1]=t1.y; sB[q*4+2]=t1.z; sB[q*4+3]=t1.w;
        sC[q*4+0]=t2.x; sC[q*4+1]=t2.y; sC[q*4+2]=t2.z; sC[q*4+3]=t2.w;
    }

    const int rowBase = blockIdx.x * 128 + warp * 16;

    float p0[4], p1[4], p2[4];
    #pragma unroll
    for (int r = 0; r < 4; r++) {
        const float* wr = W_out + (size_t)(rowBase + r) * HH;
        p0[r] = __ldg(wr + lane);
        p1[r] = __ldg(wr + lane + 32);
        p2[r] = __ldg(wr + lane + 64);
    }

    #pragma unroll
    for (int g = 0; g < 4; g++) {
        #pragma unroll
        for (int r = 0; r < 4; r++) {
            float cw0 = p0[r], cw1 = p1[r], cw2 = p2[r];
            if (g < 3) {
                const float* wr = W_out + (size_t)(rowBase + (g + 1) * 4 + r) * HH;
                p0[r] = __ldg(wr + lane);
                p1[r] = __ldg(wr + lane + 32);
                p2[r] = __ldg(wr + lane + 64);
            }
            const int rl = g * 4 + r;

            float a[16];
            #pragma unroll
            for (int bb = 0; bb < 16; bb++) a[bb] = cw0 * sA[bb] + cw1 * sB[bb] + cw2 * sC[bb];

            #pragma unroll
            for (int i = 0; i < 8; i++) {
                float send = (lane & 16) ? a[i] : a[i + 8];
                float rec  = __shfl_xor_sync(0xffffffffu, send, 16);
                float keep = (lane & 16) ? a[i + 8] : a[i];
                a[i] = keep + rec;
            }
            #pragma unroll
            for (int i = 0; i < 4; i++) {
                float send = (lane & 8) ? a[i] : a[i + 4];
                float rec  = __shfl_xor_sync(0xffffffffu, send, 8);
                float keep = (lane & 8) ? a[i + 4] : a[i];
                a[i] = keep + rec;
            }
            #pragma unroll
            for (int i = 0; i < 2; i++) {
                float send = (lane & 4) ? a[i] : a[i + 2];
                float rec  = __shfl_xor_sync(0xffffffffu, send, 4);
                float keep = (lane & 4) ? a[i + 2] : a[i];
                a[i] = keep + rec;
            }
            {
                float send = (lane & 2) ? a[0] : a[1];
                float rec  = __shfl_xor_sync(0xffffffffu, send, 2);
                float keep = (lane & 2) ? a[1] : a[0];
                a[0] = keep + rec;
            }
            float val = a[0] + __shfl_xor_sync(0xffffffffu, a[0], 1);
            val += b_out[rowBase + rl];
            if ((lane & 1) == 0) s_log[(lane >> 1) & 15][warp * 16 + rl] = val;
        }
    }
    __syncthreads();

    {
        int bb = tid >> 4, j0 = tid & 15;
        float s = 0.f;
        #pragma unroll
        for (int j = j0; j < 128; j += 16) s += __expf(s_log[bb][j]);
        #pragma unroll
        for (int o = 8; o; o >>= 1) s += __shfl_xor_sync(0xffffffffu, s, o);
        if (j0 == 0) g_psumT[bb * 256 + blockIdx.x] = s;
    }
    __threadfence();
    if (tid == 0) s_ticket = atomicAdd(&g_ctr, 1);
    __syncthreads();

    if (s_ticket == 249) {
        for (int bb = warp; bb < BB; bb += 8) {
            float s = 0.f;
            for (int p = lane; p < 250; p += 32) s += g_psumT[bb * 256 + p];
            #pragma unroll
            for (int o = 16; o; o >>= 1) s += __shfl_xor_sync(0xffffffffu, s, o);
            if (lane == 0) g_lse[bb] = __logf(s);
        }
        __syncthreads();
        __threadfence();
        if (tid == 0) atomicExch(&g_flag, 1);
    }

    if (tid == 0) {
        volatile int* vf = &g_flag;
        while (*vf == 0) __nanosleep(64);
    }
    __syncthreads();
    __threadfence();
    if (tid < BB) s_lse[tid] = g_lse[tid];
    __syncthreads();

    const int base = blockIdx.x * 128;
    #pragma unroll
    for (int idx = tid; idx < 512; idx += 256) {
        int bb = idx >> 5, q = idx & 31;
        float4 vv = *(const float4*)(&s_log[bb][q * 4]);
        float l = s_lse[bb];
        vv.x -= l; vv.y -= l; vv.z -= l; vv.w -= l;
        *(float4*)(&out_logp[bb * VV + base + q * 4]) = vv;
    }

    __threadfence();
    if (tid == 0) {
        int d = atomicAdd(&g_done, 1);
        if (d == 249) { g_ctr = 0; g_flag = 0; g_done = 0; }
    }
}

// ============================================================================
extern "C" void kernel_launch(void* const* d_in, const int* in_sizes, int n_in,
                              void* d_out, int out_size)
{
    const float* encoder_outputs = (const float*)d_in[0];
    const int*   input_ids       = (const int*)  d_in[1];
    const float* hidden          = (const float*)d_in[2];
    const float* coverage        = (const float*)d_in[3];
    const float* emb             = (const float*)d_in[4];
    const float* W_dec           = (const float*)d_in[5];
    const float* b_dec           = (const float*)d_in[6];
    const float* attn_w          = (const float*)d_in[7];
    const float* attn_b          = (const float*)d_in[8];
    const float* cvg_w           = (const float*)d_in[9];
    const float* cvg_b           = (const float*)d_in[10];
    const float* v               = (const float*)d_in[11];
    const float* W_new           = (const float*)d_in[12];
    const float* b_new           = (const float*)d_in[13];
    const float* w_ih            = (const float*)d_in[14];
    const float* w_hh            = (const float*)d_in[15];
    const float* b_ih            = (const float*)d_in[16];
    const float* b_hh            = (const float*)d_in[17];
    const float* W_pre           = (const float*)d_in[18];
    const float* b_pre           = (const float*)d_in[19];
    const float* W_out           = (const float*)d_in[20];
    const float* b_out           = (const float*)d_in[21];

    float* out = (float*)d_out;
    float* out_logp   = out;
    float* out_hidden = out + BB * VV;
    float* out_ctx2   = out_hidden + BB * HH;
    float* out_aw2    = out_ctx2 + BB * HH;
    float* out_cov2   = out_aw2 + BB * ENCL;

    const int mma_smem = (64 * 104 + JCH * 64 * 68) * (int)sizeof(float);  // 165,888
    cudaFuncSetAttribute(k1_mma, cudaFuncAttributeMaxDynamicSharedMemorySize, mma_smem);
    const int k2_smem = 2 * ENCL * HH * (int)sizeof(float);                // 49,152
    cudaFuncSetAttribute(k2_mega, cudaFuncAttributeMaxDynamicSharedMemorySize, k2_smem);

    k1_mma<<<16 * NJC + 6, 1024, mma_smem>>>(encoder_outputs, attn_w,
                                             input_ids, emb, hidden, W_dec, b_dec,
                                             coverage, cvg_w, cvg_b,
                                             w_ih, w_hh, W_new, W_pre);

    k2_mega<<<BB, 256, k2_smem>>>(encoder_outputs, coverage, hidden,
                                  W_new, b_new, w_ih, w_hh, b_ih, b_hh,
                                  W_dec, b_dec, cvg_b, v, attn_b, b_pre, W_pre,
                                  out_hidden, out_ctx2, out_aw2, out_cov2);

    k3_logits<<<250, 256>>>(W_out, b_out, out_logp);
}